// round 10
// baseline (speedup 1.0000x reference)
#include <cuda_runtime.h>
#include <cuda_bf16.h>
#include <stdint.h>
#include <cstdint>
#include <math.h>

#define B_ 2
#define S_ 1024
#define D_ 2048
#define H_ 16
#define G_ 4
#define DH_ 128
#define NQ_ 2048
#define NKV_ 512
#define NTOT_ 3072
#define MROWS_ 2048
#define PZ_ (2048*3072)      // z-stride in g_part (floats)
#define BHS_ (B_*H_*S_)      // 32768

// out-GEMM tiling: 128x128, KC=32, pitch 64 (swizzled), 3 stages
#define KC 32
#define TILE_GB 8192
#define STAGE_GB (4 * TILE_GB)
#define GEMM_SMEM (3 * STAGE_GB + 512)

// QKV GEMM tiling: 128x96
#define ATILE_QB 8192                   // 128 rows * 64B
#define BTILE_QB 6144                   // 96 rows * 64B
#define STAGE_QB (2*ATILE_QB + 2*BTILE_QB)   // 28672
#define GEMM_Q_SMEM (3 * STAGE_QB + 512)     // 86528

// Attention tiling (all swizzled, unpadded)
#define QT 128
#define KT 64
#define QTILE 32768
#define KTILE 16384
#define VTILE 16384
#define PTILE 16384
#define K_OFF 65536
#define V_OFF 131072
#define P_OFF 196608
#define ATT_SMEM 229376

#define SCALE0 0.17677669529663687f
#define SCALE1 0.125f
#define SCALE2 0.08838834764831843f

// ---------------- device scratch ----------------
__device__ float g_part[2*2048*3072];           // attention O partials (z-split)
__device__ float g_lsum[2*3*BHS_];              // attention lsum partials [z][L][bhs]
__device__ __nv_bfloat16 g_xh[MROWS_*D_];
__device__ __nv_bfloat16 g_xl[MROWS_*D_];
__device__ __nv_bfloat16 g_Wth[NTOT_*D_];
__device__ __nv_bfloat16 g_Wtl[NTOT_*D_];
__device__ __nv_bfloat16 g_Woth[D_*D_];
__device__ __nv_bfloat16 g_Wotl[D_*D_];
__device__ __nv_bfloat16 g_AOh[MROWS_*D_];
__device__ __nv_bfloat16 g_AOl[MROWS_*D_];
__device__ __nv_bfloat16 g_Qh[B_*H_*S_*DH_];
__device__ __nv_bfloat16 g_Ql[B_*H_*S_*DH_];
__device__ __nv_bfloat16 g_Kh[B_*G_*S_*DH_];
__device__ __nv_bfloat16 g_Kl[B_*G_*S_*DH_];
__device__ __nv_bfloat16 g_Vth[B_*G_*DH_*S_];   // [b,g,d,s]
__device__ __nv_bfloat16 g_Vtl[B_*G_*DH_*S_];

// ---------------- matryoshka reorder ----------------
__device__ __forceinline__ int perm16(int h, int d) {
    return (d < 32) ? (h*32 + d)
         : (d < 64) ? (512 + h*32 + (d-32))
                    : (1024 + h*64 + (d-64));
}
__device__ __forceinline__ int perm4(int g, int d) {
    return (d < 32) ? (g*32 + d)
         : (d < 64) ? (128 + g*32 + (d-32))
                    : (256 + g*64 + (d-64));
}

// ---------------- PTX helpers ----------------
__device__ __forceinline__ uint32_t smem_u32(const void* p) {
    uint32_t a;
    asm("{ .reg .u64 t; cvta.to.shared.u64 t, %1; cvt.u32.u64 %0, t; }" : "=r"(a) : "l"(p));
    return a;
}
__device__ __forceinline__ void cp_async16(uint32_t d, const void* g) {
    asm volatile("cp.async.cg.shared.global [%0], [%1], 16;" :: "r"(d), "l"(g));
}
__device__ __forceinline__ void ldsm4(uint32_t* r, uint32_t addr) {
    asm volatile("ldmatrix.sync.aligned.m8n8.x4.shared.b16 {%0,%1,%2,%3}, [%4];"
                 : "=r"(r[0]), "=r"(r[1]), "=r"(r[2]), "=r"(r[3]) : "r"(addr));
}
__device__ __forceinline__ void mma16816(float* c, const uint32_t* a, const uint32_t* b) {
    asm volatile(
        "mma.sync.aligned.m16n8k16.row.col.f32.bf16.bf16.f32 "
        "{%0,%1,%2,%3}, {%4,%5,%6,%7}, {%8,%9}, {%0,%1,%2,%3};"
        : "+f"(c[0]), "+f"(c[1]), "+f"(c[2]), "+f"(c[3])
        : "r"(a[0]), "r"(a[1]), "r"(a[2]), "r"(a[3]), "r"(b[0]), "r"(b[1]));
}
__device__ __forceinline__ void bar_pair(int id) {
    asm volatile("bar.sync %0, 64;" :: "r"(id) : "memory");
}
__device__ __forceinline__ void bf16_split(float v, __nv_bfloat16& h, __nv_bfloat16& l) {
    h = __float2bfloat16(v);
    l = __float2bfloat16(v - __bfloat162float(h));
}
__device__ __forceinline__ uint32_t swz64(int r, int c)  { return (uint32_t)r*64  + (uint32_t)((c ^ ((r>>1)&3)) << 4); }
__device__ __forceinline__ uint32_t swz128(int r, int c) { return (uint32_t)r*128 + (uint32_t)((c ^ (r&7)) << 4); }
__device__ __forceinline__ uint32_t swz256(int r, int c) { return (uint32_t)r*256 + (uint32_t)((c ^ (r&7)) << 4); }

// ================= converters =================
__global__ __launch_bounds__(256) void convx_kernel(const float* __restrict__ x) {
    int i = blockIdx.x * 256 + threadIdx.x;
    float4 v = reinterpret_cast<const float4*>(x)[i];
    __nv_bfloat16 h0,l0,h1,l1,h2,l2,h3,l3;
    bf16_split(v.x,h0,l0); bf16_split(v.y,h1,l1); bf16_split(v.z,h2,l2); bf16_split(v.w,h3,l3);
    __nv_bfloat162* ph = reinterpret_cast<__nv_bfloat162*>(g_xh);
    __nv_bfloat162* pl = reinterpret_cast<__nv_bfloat162*>(g_xl);
    ph[2*i]   = __nv_bfloat162(h0,h1); ph[2*i+1] = __nv_bfloat162(h2,h3);
    pl[2*i]   = __nv_bfloat162(l0,l1); pl[2*i+1] = __nv_bfloat162(l2,l3);
}

__global__ __launch_bounds__(256)
void tconv_qkv_kernel(const float* __restrict__ Wq, const float* __restrict__ Wk,
                      const float* __restrict__ Wv) {
    __shared__ float ts[64][65];
    const int tid = threadIdx.x;
    const int n0 = blockIdx.x * 64, k0 = blockIdx.y * 64;
    for (int idx = tid; idx < 4096; idx += 256) {
        int kk = idx >> 6, nn = idx & 63;
        int n = n0 + nn;
        const float* W; int ldw, src;
        if (n < NQ_)            { W = Wq; ldw = NQ_;  src = perm16(n >> 7, n & 127); }
        else if (n < NQ_+NKV_)  { int t = n - NQ_;        W = Wk; ldw = NKV_; src = perm4(t >> 7, t & 127); }
        else                    { int t = n - NQ_ - NKV_; W = Wv; ldw = NKV_; src = perm4(t >> 7, t & 127); }
        ts[kk][nn] = W[(size_t)(k0 + kk) * ldw + src];
    }
    __syncthreads();
    for (int idx = tid; idx < 4096; idx += 256) {
        int nn = idx >> 6, kk = idx & 63;
        __nv_bfloat16 h, l;
        bf16_split(ts[kk][nn], h, l);
        size_t o = (size_t)(n0 + nn) * D_ + k0 + kk;
        g_Wth[o] = h; g_Wtl[o] = l;
    }
}

__global__ __launch_bounds__(256)
void tconv_wo_kernel(const float* __restrict__ Wo) {
    __shared__ float ts[64][65];
    const int tid = threadIdx.x;
    const int n0 = blockIdx.x * 64, k0 = blockIdx.y * 64;
    for (int idx = tid; idx < 4096; idx += 256) {
        int kk = idx >> 6, nn = idx & 63;
        int k = k0 + kk;
        int srcrow = perm16(k >> 7, k & 127);
        ts[kk][nn] = Wo[(size_t)srcrow * D_ + n0 + nn];
    }
    __syncthreads();
    for (int idx = tid; idx < 4096; idx += 256) {
        int nn = idx >> 6, kk = idx & 63;
        __nv_bfloat16 h, l;
        bf16_split(ts[kk][nn], h, l);
        size_t o = (size_t)(n0 + nn) * D_ + k0 + kk;
        g_Woth[o] = h; g_Wotl[o] = l;
    }
}

// ================= QKV GEMM: 128x96 tiles (512 CTAs — better wave packing) =================
__global__ __launch_bounds__(256, 2)
void gemm_qkv_kernel(const __nv_bfloat16* __restrict__ Ah, const __nv_bfloat16* __restrict__ Al,
                     const __nv_bfloat16* __restrict__ Bh, const __nv_bfloat16* __restrict__ Bl,
                     const float* __restrict__ bq, const float* __restrict__ bk,
                     const float* __restrict__ bv)
{
    extern __shared__ char smem[];
    const uint32_t sb = smem_u32(smem);
    float* sBias = reinterpret_cast<float*>(smem + 3 * STAGE_QB);

    const int tid  = threadIdx.x;
    const int lane = tid & 31;
    const int wid  = tid >> 5;
    const int wm = wid >> 1;
    const int wn = wid & 1;                 // n offset wn*48
    const int n0 = blockIdx.x * 96;
    const int m0 = blockIdx.y * 128;
    const int NK = D_ / KC;     // 64

    if (tid < 96) {
        int n = n0 + tid;
        float b;
        if (n < NQ_)            b = bq[perm16(n >> 7, n & 127)];
        else if (n < NQ_+NKV_)  { int t = n - NQ_;        b = bk[perm4(t >> 7, t & 127)]; }
        else                    { int t = n - NQ_ - NKV_; b = bv[perm4(t >> 7, t & 127)]; }
        sBias[tid] = b;
    }

    const __nv_bfloat16* Ahp = Ah + (size_t)m0 * D_;
    const __nv_bfloat16* Alp = Al + (size_t)m0 * D_;
    const __nv_bfloat16* Bhp = Bh + (size_t)n0 * D_;
    const __nv_bfloat16* Blp = Bl + (size_t)n0 * D_;

    auto load_stage = [&](int chunk) {
        const uint32_t st = sb + (uint32_t)(chunk % 3) * STAGE_QB;
        const int k0 = chunk * KC;
        // A tiles: 512 chunks each
        #pragma unroll
        for (int it = 0; it < 2; it++) {
            int idx = tid + it * 256;
            int r = idx >> 2, c = idx & 3;
            cp_async16(st + swz64(r, c), Ahp + (size_t)r * D_ + k0 + c * 8);
            cp_async16(st + ATILE_QB + swz64(r, c), Alp + (size_t)r * D_ + k0 + c * 8);
        }
        // B tiles: 384 chunks each
        {
            int idx = tid;
            int r = idx >> 2, c = idx & 3;
            cp_async16(st + 2*ATILE_QB + swz64(r, c), Bhp + (size_t)r * D_ + k0 + c * 8);
            cp_async16(st + 2*ATILE_QB + BTILE_QB + swz64(r, c), Blp + (size_t)r * D_ + k0 + c * 8);
        }
        if (tid < 128) {
            int idx = tid + 256;
            int r = idx >> 2, c = idx & 3;
            cp_async16(st + 2*ATILE_QB + swz64(r, c), Bhp + (size_t)r * D_ + k0 + c * 8);
            cp_async16(st + 2*ATILE_QB + BTILE_QB + swz64(r, c), Blp + (size_t)r * D_ + k0 + c * 8);
        }
        asm volatile("cp.async.commit_group;" ::: "memory");
    };

    float acc[2][6][4];
    #pragma unroll
    for (int mi = 0; mi < 2; mi++)
        #pragma unroll
        for (int ni = 0; ni < 6; ni++)
            #pragma unroll
            for (int q = 0; q < 4; q++) acc[mi][ni][q] = 0.f;

    const int mat = lane >> 3, rin = lane & 7;
    const int arow = wm*32 + (mat & 1)*8 + rin;
    const int acb  = (mat >> 1);
    const int brow = wn*48 + (mat >> 1)*8 + rin;
    const int bcb  = (mat & 1);

    load_stage(0);
    load_stage(1);

    for (int i = 0; i < NK; i++) {
        if (i >= NK - 1) asm volatile("cp.async.wait_group 0;" ::: "memory");
        else             asm volatile("cp.async.wait_group 1;" ::: "memory");
        __syncthreads();
        if (i + 2 < NK) load_stage(i + 2);

        const uint32_t st = sb + (uint32_t)(i % 3) * STAGE_QB;
        const uint32_t aH = st, aL = st + ATILE_QB;
        const uint32_t bH = st + 2*ATILE_QB, bL = st + 2*ATILE_QB + BTILE_QB;

        #pragma unroll
        for (int kk = 0; kk < 2; kk++) {
            uint32_t ah[2][4], al[2][4];
            #pragma unroll
            for (int mi = 0; mi < 2; mi++) {
                int r = arow + mi*16;
                uint32_t off = swz64(r, kk*2 + acb);
                ldsm4(ah[mi], aH + off);
                ldsm4(al[mi], aL + off);
            }
            uint32_t bhf[6][2], blf[6][2];
            #pragma unroll
            for (int nb2 = 0; nb2 < 3; nb2++) {
                int r = brow + nb2*16;
                uint32_t off = swz64(r, kk*2 + bcb);
                uint32_t r4[4];
                ldsm4(r4, bH + off);
                bhf[2*nb2][0] = r4[0]; bhf[2*nb2][1] = r4[1];
                bhf[2*nb2+1][0] = r4[2]; bhf[2*nb2+1][1] = r4[3];
                ldsm4(r4, bL + off);
                blf[2*nb2][0] = r4[0]; blf[2*nb2][1] = r4[1];
                blf[2*nb2+1][0] = r4[2]; blf[2*nb2+1][1] = r4[3];
            }
            #pragma unroll
            for (int mi = 0; mi < 2; mi++)
                #pragma unroll
                for (int ni = 0; ni < 6; ni++) {
                    mma16816(acc[mi][ni], ah[mi], bhf[ni]);
                    mma16816(acc[mi][ni], al[mi], bhf[ni]);
                    mma16816(acc[mi][ni], ah[mi], blf[ni]);
                }
        }
    }

    // ---------- epilogue: per-column region routing ----------
    const int g = lane >> 2, tig = lane & 3;
    #pragma unroll
    for (int mi = 0; mi < 2; mi++)
        #pragma unroll
        for (int ni = 0; ni < 6; ni++) {
            int lcol = wn*48 + ni*8 + tig*2;
            int col = n0 + lcol;
            float b0 = sBias[lcol], b1 = sBias[lcol + 1];
            #pragma unroll
            for (int half = 0; half < 2; half++) {
                int row = m0 + wm*32 + mi*16 + g + half*8;
                float vx = acc[mi][ni][half*2+0] + b0;
                float vy = acc[mi][ni][half*2+1] + b1;
                int bb = row >> 10, s = row & 1023;
                __nv_bfloat16 hx,lx,hy,ly;
                bf16_split(vx,hx,lx); bf16_split(vy,hy,ly);
                if (col < NQ_) {
                    int h = col >> 7, d = col & 127;
                    size_t o = ((size_t)((bb*H_ + h)*S_ + s))*DH_ + d;
                    *reinterpret_cast<__nv_bfloat162*>(g_Qh + o) = __nv_bfloat162(hx,hy);
                    *reinterpret_cast<__nv_bfloat162*>(g_Ql + o) = __nv_bfloat162(lx,ly);
                } else if (col < NQ_+NKV_) {
                    int t = col - NQ_;
                    int gg = t >> 7, d = t & 127;
                    size_t o = ((size_t)((bb*G_ + gg)*S_ + s))*DH_ + d;
                    *reinterpret_cast<__nv_bfloat162*>(g_Kh + o) = __nv_bfloat162(hx,hy);
                    *reinterpret_cast<__nv_bfloat162*>(g_Kl + o) = __nv_bfloat162(lx,ly);
                } else {
                    int t = col - NQ_ - NKV_;
                    int gg = t >> 7, d = t & 127;
                    size_t o = ((size_t)(bb*G_ + gg)*DH_ + d)*S_ + s;
                    g_Vth[o] = hx; g_Vtl[o] = lx;
                    g_Vth[o + S_] = hy; g_Vtl[o + S_] = ly;
                }
            }
        }
}

// ================= out GEMM: 128x128 (single wave already) =================
__global__ __launch_bounds__(256, 2)
void gemm_out_kernel(const __nv_bfloat16* __restrict__ Ah, const __nv_bfloat16* __restrict__ Al,
                     const __nv_bfloat16* __restrict__ Bh, const __nv_bfloat16* __restrict__ Bl,
                     float* __restrict__ outp, const float* __restrict__ bo)
{
    extern __shared__ char smem[];
    const uint32_t sb = smem_u32(smem);
    float* sBias = reinterpret_cast<float*>(smem + 3 * STAGE_GB);

    const int tid  = threadIdx.x;
    const int lane = tid & 31;
    const int wid  = tid >> 5;
    const int wm = wid >> 1;
    const int wn = wid & 1;
    const int n0 = blockIdx.x * 128;
    const int m0 = blockIdx.y * 128;
    const int NK = D_ / KC;

    if (tid < 128) sBias[tid] = bo[n0 + tid];

    const __nv_bfloat16* srcs[4] = {
        Ah + (size_t)m0 * D_, Al + (size_t)m0 * D_,
        Bh + (size_t)n0 * D_, Bl + (size_t)n0 * D_ };

    auto load_stage = [&](int chunk) {
        const uint32_t st = sb + (uint32_t)(chunk % 3) * STAGE_GB;
        const int k0 = chunk * KC;
        #pragma unroll
        for (int t = 0; t < 4; t++) {
            const __nv_bfloat16* s = srcs[t];
            const uint32_t tb = st + t * TILE_GB;
            #pragma unroll
            for (int it = 0; it < 2; it++) {
                int idx = tid + it * 256;
                int r = idx >> 2, c = idx & 3;
                cp_async16(tb + swz64(r, c), s + (size_t)r * D_ + k0 + c * 8);
            }
        }
        asm volatile("cp.async.commit_group;" ::: "memory");
    };

    float acc[2][8][4];
    #pragma unroll
    for (int mi = 0; mi < 2; mi++)
        #pragma unroll
        for (int ni = 0; ni < 8; ni++)
            #pragma unroll
            for (int q = 0; q < 4; q++) acc[mi][ni][q] = 0.f;

    const int mat = lane >> 3, rin = lane & 7;
    const int arow = wm*32 + (mat & 1)*8 + rin;
    const int acb  = (mat >> 1);
    const int brow = wn*64 + (mat >> 1)*8 + rin;
    const int bcb  = (mat & 1);

    load_stage(0);
    load_stage(1);

    for (int i = 0; i < NK; i++) {
        if (i >= NK - 1) asm volatile("cp.async.wait_group 0;" ::: "memory");
        else             asm volatile("cp.async.wait_group 1;" ::: "memory");
        __syncthreads();
        if (i + 2 < NK) load_stage(i + 2);

        const uint32_t st = sb + (uint32_t)(i % 3) * STAGE_GB;
        const uint32_t aH = st, aL = st + TILE_GB, bH = st + 2*TILE_GB, bL = st + 3*TILE_GB;

        #pragma unroll
        for (int kk = 0; kk < 2; kk++) {
            uint32_t ah[2][4], al[2][4];
            #pragma unroll
            for (int mi = 0; mi < 2; mi++) {
                int r = arow + mi*16;
                uint32_t off = swz64(r, kk*2 + acb);
                ldsm4(ah[mi], aH + off);
                ldsm4(al[mi], aL + off);
            }
            #pragma unroll
            for (int half = 0; half < 2; half++) {
                uint32_t bhf[4][2], blf[4][2];
                #pragma unroll
                for (int nb2 = 0; nb2 < 2; nb2++) {
                    int r = brow + (half*2 + nb2)*16;
                    uint32_t off = swz64(r, kk*2 + bcb);
                    uint32_t r4[4];
                    ldsm4(r4, bH + off);
                    bhf[2*nb2][0] = r4[0]; bhf[2*nb2][1] = r4[1];
                    bhf[2*nb2+1][0] = r4[2]; bhf[2*nb2+1][1] = r4[3];
                    ldsm4(r4, bL + off);
                    blf[2*nb2][0] = r4[0]; blf[2*nb2][1] = r4[1];
                    blf[2*nb2+1][0] = r4[2]; blf[2*nb2+1][1] = r4[3];
                }
                #pragma unroll
                for (int mi = 0; mi < 2; mi++)
                    #pragma unroll
                    for (int nf = 0; nf < 4; nf++) {
                        int ni = half*4 + nf;
                        mma16816(acc[mi][ni], ah[mi], bhf[nf]);
                        mma16816(acc[mi][ni], al[mi], bhf[nf]);
                        mma16816(acc[mi][ni], ah[mi], blf[nf]);
                    }
            }
        }
    }

    const int g = lane >> 2, tig = lane & 3;
    #pragma unroll
    for (int mi = 0; mi < 2; mi++)
        #pragma unroll
        for (int ni = 0; ni < 8; ni++) {
            int col = wn*64 + ni*8 + tig*2;
            float b0 = sBias[col], b1 = sBias[col + 1];
            #pragma unroll
            for (int half = 0; half < 2; half++) {
                int row = m0 + wm*32 + mi*16 + g + half*8;
                *reinterpret_cast<float2*>(outp + (size_t)row * D_ + n0 + col) =
                    make_float2(acc[mi][ni][half*2+0] + b0, acc[mi][ni][half*2+1] + b1);
            }
        }
}

// ================= HMMA matryoshka flash attention, split-KV x2 =================
__global__ __launch_bounds__(512, 1)
void attn_mma_kernel()
{
    extern __shared__ char smem[];
    const uint32_t sb = smem_u32(smem);
    const int tid = threadIdx.x, lane = tid & 31, wid = tid >> 5;
    const int qt2 = (S_/QT - 1) - blockIdx.x;   // heavy CTAs first
    const int h = blockIdx.y;
    const int zz = blockIdx.z & 1, b = blockIdx.z >> 1;
    const int g = h >> 2;
    const int q0 = qt2 * QT;
    const int ktS = zz * (qt2 + 1);
    const int ktE = ktS + qt2 + 1;
    const int wq = (wid >> 1) * 16;
    const int wk = wid & 1;
    const int barid = 1 + (wid >> 1);
    const int mat = lane >> 3, rin = lane & 7;
    const int gq = lane >> 2, tig = lane & 3;

    const __nv_bfloat16* Khp = g_Kh + ((size_t)(b*G_ + g) * S_) * DH_;
    const __nv_bfloat16* Klp = g_Kl + ((size_t)(b*G_ + g) * S_) * DH_;
    const __nv_bfloat16* Vhp = g_Vth + (size_t)(b*G_ + g) * DH_ * S_;
    const __nv_bfloat16* Vlp = g_Vtl + (size_t)(b*G_ + g) * DH_ * S_;
    const __nv_bfloat16* Qhp = g_Qh + ((size_t)(b*H_ + h) * S_ + q0) * DH_;
    const __nv_bfloat16* Qlp = g_Ql + ((size_t)(b*H_ + h) * S_ + q0) * DH_;

    auto issue_KV = [&](int kt) {
        const uint32_t kst = sb + K_OFF + (uint32_t)(kt & 1) * (2*KTILE);
        const uint32_t vst = sb + V_OFF + (uint32_t)(kt & 1) * (2*VTILE);
        const int k0 = kt * KT;
        #pragma unroll
        for (int i = 0; i < 2; i++) {
            int idx = tid + i * 512;
            { int r = idx >> 4, c = idx & 15;
              cp_async16(kst + swz256(r, c), Khp + (size_t)(k0 + r)*DH_ + c*8);
              cp_async16(kst + KTILE + swz256(r, c), Klp + (size_t)(k0 + r)*DH_ + c*8); }
            { int r = idx >> 3, c = idx & 7;
              cp_async16(vst + swz128(r, c), Vhp + (size_t)r*S_ + k0 + c*8);
              cp_async16(vst + VTILE + swz128(r, c), Vlp + (size_t)r*S_ + k0 + c*8); }
        }
        asm volatile("cp.async.commit_group;" ::: "memory");
    };

    #pragma unroll
    for (int i = 0; i < 4; i++) {
        int idx = tid + i * 512; int r = idx >> 4, c = idx & 15;
        cp_async16(sb + swz256(r, c), Qhp + (size_t)r*DH_ + c*8);
        cp_async16(sb + QTILE + swz256(r, c), Qlp + (size_t)r*DH_ + c*8);
    }
    issue_KV(ktS);

    float o0[2][4] = {}, o1[2][4] = {}, o2[4][4] = {};
    float lsum[3][2] = {};

    const int rq = wq + (mat & 1)*8 + rin;
    const uint32_t qrow_off = (uint32_t)rq * 256;
    const int qsw = rq & 7;
    const uint32_t prow_off = (uint32_t)rq * 128;
    char* pwp = smem + P_OFF;
    float* lred = reinterpret_cast<float*>(smem + P_OFF);

    for (int kt = ktS; kt < ktE; kt++) {
        asm volatile("cp.async.wait_group 0;" ::: "memory");
        __syncthreads();
        if (kt + 1 < ktE) issue_KV(kt + 1);

        const int k0 = kt * KT;
        const uint32_t kst = sb + K_OFF + (uint32_t)(kt & 1) * (2*KTILE);
        const uint32_t vst = sb + V_OFF + (uint32_t)(kt & 1) * (2*VTILE);

        float acc[4][4];
        #pragma unroll
        for (int nb = 0; nb < 4; nb++)
            #pragma unroll
            for (int q = 0; q < 4; q++) acc[nb][q] = 0.f;

        auto qk_steps = [&](int kkA, int kkB) {
            #pragma unroll
            for (int kk = kkA; kk < kkB; kk++) {
                uint32_t qh[4], ql[4];
                uint32_t qoff = qrow_off + (uint32_t)(((kk*2 + (mat>>1)) ^ qsw) << 4);
                ldsm4(qh, sb + qoff);
                ldsm4(ql, sb + QTILE + qoff);
                uint32_t bh[4][2], bl[4][2];
                #pragma unroll
                for (int nb2 = 0; nb2 < 2; nb2++) {
                    int rk = wk*32 + nb2*16 + (mat >> 1)*8 + rin;
                    uint32_t off = swz256(rk, kk*2 + (mat & 1));
                    uint32_t r4[4];
                    ldsm4(r4, kst + off);
                    bh[2*nb2][0] = r4[0]; bh[2*nb2][1] = r4[1];
                    bh[2*nb2+1][0] = r4[2]; bh[2*nb2+1][1] = r4[3];
                    ldsm4(r4, kst + KTILE + off);
                    bl[2*nb2][0] = r4[0]; bl[2*nb2][1] = r4[1];
                    bl[2*nb2+1][0] = r4[2]; bl[2*nb2+1][1] = r4[3];
                }
                #pragma unroll
                for (int nb = 0; nb < 4; nb++) {
                    mma16816(acc[nb], qh, bh[nb]);
                    mma16816(acc[nb], qh, bl[nb]);
                    mma16816(acc[nb], ql, bh[nb]);
                }
            }
        };

        auto do_exp = [&](float scale, float* ls) {
            const int r0g = q0 + wq + gq, r1g = r0g + 8;
            const bool need_mask = (k0 + wk*32 + 31 > q0 + wq);
            #pragma unroll
            for (int nb = 0; nb < 4; nb++) {
                int colg = k0 + wk*32 + nb*8 + tig*2;
                float p0 = __expf(acc[nb][0] * scale);
                float p1 = __expf(acc[nb][1] * scale);
                float p2 = __expf(acc[nb][2] * scale);
                float p3 = __expf(acc[nb][3] * scale);
                if (need_mask) {
                    if (colg     > r0g) p0 = 0.f;
                    if (colg + 1 > r0g) p1 = 0.f;
                    if (colg     > r1g) p2 = 0.f;
                    if (colg + 1 > r1g) p3 = 0.f;
                }
                ls[0] += p0 + p1; ls[1] += p2 + p3;
                __nv_bfloat16 h0,l0,h1,l1,h2,l2,h3,l3;
                bf16_split(p0,h0,l0); bf16_split(p1,h1,l1);
                bf16_split(p2,h2,l2); bf16_split(p3,h3,l3);
                int rw0 = wq + gq, rw1 = rw0 + 8;
                int c = wk*4 + nb;
                uint32_t o0b = swz128(rw0, c) + tig*4;
                uint32_t o1b = swz128(rw1, c) + tig*4;
                *reinterpret_cast<__nv_bfloat162*>(pwp + o0b)          = __nv_bfloat162(h0,h1);
                *reinterpret_cast<__nv_bfloat162*>(pwp + o0b + PTILE)  = __nv_bfloat162(l0,l1);
                *reinterpret_cast<__nv_bfloat162*>(pwp + o1b)          = __nv_bfloat162(h2,h3);
                *reinterpret_cast<__nv_bfloat162*>(pwp + o1b + PTILE)  = __nv_bfloat162(l2,l3);
            }
        };

        auto do_pv = [&](int dbase, float (*oacc)[4], int nb2cnt) {
            #pragma unroll
            for (int kk2 = 0; kk2 < 4; kk2++) {
                uint32_t pah[4], pal[4];
                uint32_t poff = prow_off + (uint32_t)(((kk2*2 + (mat>>1)) ^ qsw) << 4);
                ldsm4(pah, sb + P_OFF + poff);
                ldsm4(pal, sb + P_OFF + PTILE + poff);
                for (int nb2 = 0; nb2 < nb2cnt; nb2++) {
                    int rv = dbase + nb2*16 + (mat >> 1)*8 + rin;
                    uint32_t voff = swz128(rv, kk2*2 + (mat & 1));
                    uint32_t r4[4], s4[4];
                    ldsm4(r4, vst + voff);
                    ldsm4(s4, vst + VTILE + voff);
                    uint32_t vh0[2] = {r4[0], r4[1]}, vh1[2] = {r4[2], r4[3]};
                    uint32_t vl0[2] = {s4[0], s4[1]}, vl1[2] = {s4[2], s4[3]};
                    mma16816(oacc[2*nb2],   pah, vh0);
                    mma16816(oacc[2*nb2],   pah, vl0);
                    mma16816(oacc[2*nb2],   pal, vh0);
                    mma16816(oacc[2*nb2+1], pah, vh1);
                    mma16816(oacc[2*nb2+1], pah, vl1);
                    mma16816(oacc[2*nb2+1], pal, vh1);
                }
            }
        };

        qk_steps(0, 2);
        do_exp(SCALE0, lsum[0]);
        bar_pair(barid);
        do_pv(0 + wk*16, o0, 1);
        qk_steps(2, 4);
        bar_pair(barid);
        do_exp(SCALE1, lsum[1]);
        bar_pair(barid);
        do_pv(32 + wk*16, o1, 1);
        qk_steps(4, 8);
        bar_pair(barid);
        do_exp(SCALE2, lsum[2]);
        bar_pair(barid);
        do_pv(64 + wk*32, o2, 2);
    }

    // reduce row sums: quad via shfl, k-halves via smem (lred aliases P)
    #pragma unroll
    for (int L = 0; L < 3; L++)
        #pragma unroll
        for (int j = 0; j < 2; j++) {
            lsum[L][j] += __shfl_xor_sync(0xffffffffu, lsum[L][j], 1);
            lsum[L][j] += __shfl_xor_sync(0xffffffffu, lsum[L][j], 2);
        }
    __syncthreads();
    if (tig == 0) {
        #pragma unroll
        for (int L = 0; L < 3; L++) {
            lred[L*256 + (wq + gq)*2 + wk]     = lsum[L][0];
            lred[L*256 + (wq + gq + 8)*2 + wk] = lsum[L][1];
        }
    }
    __syncthreads();

    const int r0 = wq + gq, r1 = r0 + 8;

    if (wk == 0 && tig == 0) {
        int idx0 = (b*H_ + h)*S_ + q0 + r0;
        int idx1 = idx0 + 8;
        #pragma unroll
        for (int L = 0; L < 3; L++) {
            g_lsum[(zz*3 + L)*BHS_ + idx0] = lred[L*256 + r0*2] + lred[L*256 + r0*2 + 1];
            g_lsum[(zz*3 + L)*BHS_ + idx1] = lred[L*256 + r1*2] + lred[L*256 + r1*2 + 1];
        }
    }

    float* part = g_part + (size_t)zz * PZ_;
    size_t base0 = ((size_t)(b*S_ + q0 + r0)) * D_ + (size_t)h * DH_;
    size_t base1 = ((size_t)(b*S_ + q0 + r1)) * D_ + (size_t)h * DH_;
    #pragma unroll
    for (int j = 0; j < 2; j++) {
        int d = wk*16 + j*8 + tig*2;
        *reinterpret_cast<float2*>(part + base0 + d)      = make_float2(o0[j][0], o0[j][1]);
        *reinterpret_cast<float2*>(part + base1 + d)      = make_float2(o0[j][2], o0[j][3]);
        *reinterpret_cast<float2*>(part + base0 + 32 + d) = make_float2(o1[j][0], o1[j][1]);
        *reinterpret_cast<float2*>(part + base1 + 32 + d) = make_float2(o1[j][2], o1[j][3]);
    }
    #pragma unroll
    for (int j = 0; j < 4; j++) {
        int d = 64 + wk*32 + j*8 + tig*2;
        *reinterpret_cast<float2*>(part + base0 + d) = make_float2(o2[j][0], o2[j][1]);
        *reinterpret_cast<float2*>(part + base1 + d) = make_float2(o2[j][2], o2[j][3]);
    }
}

// ================= attention combine =================
__global__ __launch_bounds__(256)
void attn_combine()
{
    const int m = blockIdx.x;
    const int col = blockIdx.y * 512 + threadIdx.x * 2;
    float2 p0 = *reinterpret_cast<const float2*>(g_part + (size_t)m*D_ + col);
    float2 p1 = *reinterpret_cast<const float2*>(g_part + PZ_ + (size_t)m*D_ + col);
    const int h = col >> 7, d = col & 127;
    const int L = (d < 32) ? 0 : (d < 64) ? 1 : 2;
    const int b = m >> 10, s = m & 1023;
    const int idx = (b*H_ + h)*S_ + s;
    float ls = g_lsum[L*BHS_ + idx] + g_lsum[(3 + L)*BHS_ + idx];
    float inv = 1.f / ls;
    float v0 = (p0.x + p1.x) * inv;
    float v1 = (p0.y + p1.y) * inv;
    __nv_bfloat16 h0,l0,h1,l1;
    bf16_split(v0,h0,l0); bf16_split(v1,h1,l1);
    size_t o = (size_t)m * D_ + col;
    *reinterpret_cast<__nv_bfloat162*>(g_AOh + o) = __nv_bfloat162(h0,h1);
    *reinterpret_cast<__nv_bfloat162*>(g_AOl + o) = __nv_bfloat162(l0,l1);
}

// ================= launch =================
extern "C" void kernel_launch(void* const* d_in, const int* in_sizes, int n_in,
                              void* d_out, int out_size)
{
    (void)in_sizes; (void)n_in; (void)out_size;
    const float* x  = (const float*)d_in[0];
    const float* Wq = (const float*)d_in[2];
    const float* bq = (const float*)d_in[3];
    const float* Wk = (const float*)d_in[4];
    const float* bk = (const float*)d_in[5];
    const float* Wv = (const float*)d_in[6];
    const float* bv = (const float*)d_in[7];
    const float* Wo = (const float*)d_in[8];
    const float* bo = (const float*)d_in[9];
    float* out = (float*)d_out;

    convx_kernel<<<MROWS_*D_/4/256, 256>>>(x);
    tconv_qkv_kernel<<<dim3(NTOT_/64, D_/64), 256>>>(Wq, Wk, Wv);
    tconv_wo_kernel<<<dim3(D_/64, D_/64), 256>>>(Wo);

    static __nv_bfloat16 *pxh = nullptr, *pxl, *pwth, *pwtl, *pwoth, *pwotl, *paoh, *paol;
    if (!pxh) {
        cudaGetSymbolAddress((void**)&pxh, g_xh);
        cudaGetSymbolAddress((void**)&pxl, g_xl);
        cudaGetSymbolAddress((void**)&pwth, g_Wth);
        cudaGetSymbolAddress((void**)&pwtl, g_Wtl);
        cudaGetSymbolAddress((void**)&pwoth, g_Woth);
        cudaGetSymbolAddress((void**)&pwotl, g_Wotl);
        cudaGetSymbolAddress((void**)&paoh, g_AOh);
        cudaGetSymbolAddress((void**)&paol, g_AOl);
    }

    static bool attr_set = false;
    if (!attr_set) {
        cudaFuncSetAttribute(gemm_qkv_kernel, cudaFuncAttributeMaxDynamicSharedMemorySize, GEMM_Q_SMEM);
        cudaFuncSetAttribute(gemm_out_kernel, cudaFuncAttributeMaxDynamicSharedMemorySize, GEMM_SMEM);
        cudaFuncSetAttribute(attn_mma_kernel, cudaFuncAttributeMaxDynamicSharedMemorySize, ATT_SMEM);
        attr_set = true;
    }

    // QKV GEMM: 128x96 tiles, 512 CTAs
    gemm_qkv_kernel<<<dim3(NTOT_/96, MROWS_/128), 256, GEMM_Q_SMEM>>>(
        pxh, pxl, pwth, pwtl, bq, bk, bv);

    // split-KV attention: z = b*2 + kv-half
    attn_mma_kernel<<<dim3(S_/QT, H_, B_*2), 512, ATT_SMEM>>>();
    attn_combine<<<dim3(MROWS_, 4), 256>>>();

    gemm_out_kernel<<<dim3(D_/128, MROWS_/128), 256, GEMM_SMEM>>>(
        paoh, paol, pwoth, pwotl, out, bo);
}

// round 12
// speedup vs baseline: 1.0050x; 1.0050x over previous
#include <cuda_runtime.h>
#include <cuda_bf16.h>
#include <stdint.h>
#include <cstdint>
#include <math.h>

#define B_ 2
#define S_ 1024
#define D_ 2048
#define H_ 16
#define G_ 4
#define DH_ 128
#define NQ_ 2048
#define NKV_ 512
#define NTOT_ 3072
#define MROWS_ 2048
#define PZ_ (2048*3072)
#define BHS_ (B_*H_*S_)

#define KC 32
#define TILE_GB 8192
#define STAGE_GB (4 * TILE_GB)
#define GEMM_SMEM (3 * STAGE_GB + 512)

#define QT 128
#define KT 64
#define QTILE 32768
#define KTILE 16384
#define VTILE 16384
#define PTILE 16384
#define K_OFF 65536
#define V_OFF 131072
#define P_OFF 196608
#define ATT_SMEM 229376

#define SCALE0 0.17677669529663687f
#define SCALE1 0.125f
#define SCALE2 0.08838834764831843f

// ---------------- device scratch ----------------
__device__ float g_part[2*2048*3072];
__device__ float g_lsum[2*3*BHS_];
__device__ __nv_bfloat16 g_xh[MROWS_*D_];
__device__ __nv_bfloat16 g_xl[MROWS_*D_];
__device__ __nv_bfloat16 g_Wth[NTOT_*D_];
__device__ __nv_bfloat16 g_Wtl[NTOT_*D_];
__device__ __nv_bfloat16 g_Woth[D_*D_];
__device__ __nv_bfloat16 g_Wotl[D_*D_];
__device__ __nv_bfloat16 g_AOh[MROWS_*D_];
__device__ __nv_bfloat16 g_AOl[MROWS_*D_];
__device__ __nv_bfloat16 g_Qh[B_*H_*S_*DH_];
__device__ __nv_bfloat16 g_Ql[B_*H_*S_*DH_];
__device__ __nv_bfloat16 g_Kh[B_*G_*S_*DH_];
__device__ __nv_bfloat16 g_Kl[B_*G_*S_*DH_];
__device__ __nv_bfloat16 g_Vth[B_*G_*DH_*S_];
__device__ __nv_bfloat16 g_Vtl[B_*G_*DH_*S_];

// ---------------- matryoshka reorder ----------------
__device__ __forceinline__ int perm16(int h, int d) {
    return (d < 32) ? (h*32 + d)
         : (d < 64) ? (512 + h*32 + (d-32))
                    : (1024 + h*64 + (d-64));
}
__device__ __forceinline__ int perm4(int g, int d) {
    return (d < 32) ? (g*32 + d)
         : (d < 64) ? (128 + g*32 + (d-32))
                    : (256 + g*64 + (d-64));
}

// ---------------- PTX helpers ----------------
__device__ __forceinline__ uint32_t smem_u32(const void* p) {
    uint32_t a;
    asm("{ .reg .u64 t; cvta.to.shared.u64 t, %1; cvt.u32.u64 %0, t; }" : "=r"(a) : "l"(p));
    return a;
}
__device__ __forceinline__ void cp_async16(uint32_t d, const void* g) {
    asm volatile("cp.async.cg.shared.global [%0], [%1], 16;" :: "r"(d), "l"(g));
}
__device__ __forceinline__ void ldsm4(uint32_t* r, uint32_t addr) {
    asm volatile("ldmatrix.sync.aligned.m8n8.x4.shared.b16 {%0,%1,%2,%3}, [%4];"
                 : "=r"(r[0]), "=r"(r[1]), "=r"(r[2]), "=r"(r[3]) : "r"(addr));
}
__device__ __forceinline__ void mma16816(float* c, const uint32_t* a, const uint32_t* b) {
    asm volatile(
        "mma.sync.aligned.m16n8k16.row.col.f32.bf16.bf16.f32 "
        "{%0,%1,%2,%3}, {%4,%5,%6,%7}, {%8,%9}, {%0,%1,%2,%3};"
        : "+f"(c[0]), "+f"(c[1]), "+f"(c[2]), "+f"(c[3])
        : "r"(a[0]), "r"(a[1]), "r"(a[2]), "r"(a[3]), "r"(b[0]), "r"(b[1]));
}
__device__ __forceinline__ void bar_pair(int id) {
    asm volatile("bar.sync %0, 64;" :: "r"(id) : "memory");
}
__device__ __forceinline__ void bf16_split(float v, __nv_bfloat16& h, __nv_bfloat16& l) {
    h = __float2bfloat16(v);
    l = __float2bfloat16(v - __bfloat162float(h));
}
__device__ __forceinline__ uint32_t swz64(int r, int c)  { return (uint32_t)r*64  + (uint32_t)((c ^ ((r>>1)&3)) << 4); }
__device__ __forceinline__ uint32_t swz128(int r, int c) { return (uint32_t)r*128 + (uint32_t)((c ^ (r&7)) << 4); }
__device__ __forceinline__ uint32_t swz256(int r, int c) { return (uint32_t)r*256 + (uint32_t)((c ^ (r&7)) << 4); }

// ================= converters =================
__global__ __launch_bounds__(256) void convx_kernel(const float* __restrict__ x) {
    int i = blockIdx.x * 256 + threadIdx.x;
    float4 v = reinterpret_cast<const float4*>(x)[i];
    __nv_bfloat16 h0,l0,h1,l1,h2,l2,h3,l3;
    bf16_split(v.x,h0,l0); bf16_split(v.y,h1,l1); bf16_split(v.z,h2,l2); bf16_split(v.w,h3,l3);
    __nv_bfloat162* ph = reinterpret_cast<__nv_bfloat162*>(g_xh);
    __nv_bfloat162* pl = reinterpret_cast<__nv_bfloat162*>(g_xl);
    ph[2*i]   = __nv_bfloat162(h0,h1); ph[2*i+1] = __nv_bfloat162(h2,h3);
    pl[2*i]   = __nv_bfloat162(l0,l1); pl[2*i+1] = __nv_bfloat162(l2,l3);
}

__global__ __launch_bounds__(256)
void tconv_qkv_kernel(const float* __restrict__ Wq, const float* __restrict__ Wk,
                      const float* __restrict__ Wv) {
    __shared__ float ts[64][65];
    const int tid = threadIdx.x;
    const int n0 = blockIdx.x * 64, k0 = blockIdx.y * 64;
    for (int idx = tid; idx < 4096; idx += 256) {
        int kk = idx >> 6, nn = idx & 63;
        int n = n0 + nn;
        const float* W; int ldw, src;
        if (n < NQ_)            { W = Wq; ldw = NQ_;  src = perm16(n >> 7, n & 127); }
        else if (n < NQ_+NKV_)  { int t = n - NQ_;        W = Wk; ldw = NKV_; src = perm4(t >> 7, t & 127); }
        else                    { int t = n - NQ_ - NKV_; W = Wv; ldw = NKV_; src = perm4(t >> 7, t & 127); }
        ts[kk][nn] = W[(size_t)(k0 + kk) * ldw + src];
    }
    __syncthreads();
    for (int idx = tid; idx < 4096; idx += 256) {
        int nn = idx >> 6, kk = idx & 63;
        __nv_bfloat16 h, l;
        bf16_split(ts[kk][nn], h, l);
        size_t o = (size_t)(n0 + nn) * D_ + k0 + kk;
        g_Wth[o] = h; g_Wtl[o] = l;
    }
}

__global__ __launch_bounds__(256)
void tconv_wo_kernel(const float* __restrict__ Wo) {
    __shared__ float ts[64][65];
    const int tid = threadIdx.x;
    const int n0 = blockIdx.x * 64, k0 = blockIdx.y * 64;
    for (int idx = tid; idx < 4096; idx += 256) {
        int kk = idx >> 6, nn = idx & 63;
        int k = k0 + kk;
        int srcrow = perm16(k >> 7, k & 127);
        ts[kk][nn] = Wo[(size_t)srcrow * D_ + n0 + nn];
    }
    __syncthreads();
    for (int idx = tid; idx < 4096; idx += 256) {
        int nn = idx >> 6, kk = idx & 63;
        __nv_bfloat16 h, l;
        bf16_split(ts[kk][nn], h, l);
        size_t o = (size_t)(n0 + nn) * D_ + k0 + kk;
        g_Woth[o] = h; g_Wotl[o] = l;
    }
}

// ================= mma.sync bf16x3 GEMM (product-major MMA order) =================
template<int MODE>
__global__ __launch_bounds__(256, 2)
void gemm_mma_kernel(const __nv_bfloat16* __restrict__ Ah, const __nv_bfloat16* __restrict__ Al,
                     const __nv_bfloat16* __restrict__ Bh, const __nv_bfloat16* __restrict__ Bl,
                     float* __restrict__ outp,
                     const float* __restrict__ bq, const float* __restrict__ bk,
                     const float* __restrict__ bv)
{
    extern __shared__ char smem[];
    const uint32_t sb = smem_u32(smem);
    float* sBias = reinterpret_cast<float*>(smem + 3 * STAGE_GB);

    const int tid  = threadIdx.x;
    const int lane = tid & 31;
    const int wid  = tid >> 5;
    const int wm = wid >> 1;
    const int wn = wid & 1;
    const int n0 = blockIdx.x * 128;
    const int m0 = blockIdx.y * 128;
    const int NK = D_ / KC;

    if (tid < 128) {
        int n = n0 + tid;
        float b;
        if (MODE == 0) {
            if (n < NQ_)            b = bq[perm16(n >> 7, n & 127)];
            else if (n < NQ_+NKV_)  { int t = n - NQ_;        b = bk[perm4(t >> 7, t & 127)]; }
            else                    { int t = n - NQ_ - NKV_; b = bv[perm4(t >> 7, t & 127)]; }
        } else b = bq[n];
        sBias[tid] = b;
    }

    const __nv_bfloat16* srcs[4] = {
        Ah + (size_t)m0 * D_, Al + (size_t)m0 * D_,
        Bh + (size_t)n0 * D_, Bl + (size_t)n0 * D_ };

    auto load_stage = [&](int chunk) {
        const uint32_t st = sb + (uint32_t)(chunk % 3) * STAGE_GB;
        const int k0 = chunk * KC;
        #pragma unroll
        for (int t = 0; t < 4; t++) {
            const __nv_bfloat16* s = srcs[t];
            const uint32_t tb = st + t * TILE_GB;
            #pragma unroll
            for (int it = 0; it < 2; it++) {
                int idx = tid + it * 256;
                int r = idx >> 2, c = idx & 3;
                cp_async16(tb + swz64(r, c), s + (size_t)r * D_ + k0 + c * 8);
            }
        }
        asm volatile("cp.async.commit_group;" ::: "memory");
    };

    float acc[2][8][4];
    #pragma unroll
    for (int mi = 0; mi < 2; mi++)
        #pragma unroll
        for (int ni = 0; ni < 8; ni++)
            #pragma unroll
            for (int q = 0; q < 4; q++) acc[mi][ni][q] = 0.f;

    const int mat = lane >> 3, rin = lane & 7;
    const int arow = wm*32 + (mat & 1)*8 + rin;
    const int acb  = (mat >> 1);
    const int brow = wn*64 + (mat >> 1)*8 + rin;
    const int bcb  = (mat & 1);

    load_stage(0);
    load_stage(1);

    for (int i = 0; i < NK; i++) {
        if (i >= NK - 1) asm volatile("cp.async.wait_group 0;" ::: "memory");
        else             asm volatile("cp.async.wait_group 1;" ::: "memory");
        __syncthreads();
        if (i + 2 < NK) load_stage(i + 2);

        const uint32_t st = sb + (uint32_t)(i % 3) * STAGE_GB;
        const uint32_t aH = st, aL = st + TILE_GB, bH = st + 2*TILE_GB, bL = st + 3*TILE_GB;

        #pragma unroll
        for (int kk = 0; kk < 2; kk++) {
            uint32_t ah[2][4], al[2][4];
            #pragma unroll
            for (int mi = 0; mi < 2; mi++) {
                int r = arow + mi*16;
                uint32_t off = swz64(r, kk*2 + acb);
                ldsm4(ah[mi], aH + off);
                ldsm4(al[mi], aL + off);
            }
            uint32_t bhf[8][2], blf[8][2];
            #pragma unroll
            for (int nb2 = 0; nb2 < 4; nb2++) {
                int r = brow + nb2*16;
                uint32_t off = swz64(r, kk*2 + bcb);
                uint32_t r4[4];
                ldsm4(r4, bH + off);
                bhf[2*nb2][0] = r4[0]; bhf[2*nb2][1] = r4[1];
                bhf[2*nb2+1][0] = r4[2]; bhf[2*nb2+1][1] = r4[3];
                ldsm4(r4, bL + off);
                blf[2*nb2][0] = r4[0]; blf[2*nb2][1] = r4[1];
                blf[2*nb2+1][0] = r4[2]; blf[2*nb2+1][1] = r4[3];
            }
            // product-major: 16 independent MMAs between same-acc reuse
            #pragma unroll
            for (int mi = 0; mi < 2; mi++)
                #pragma unroll
                for (int ni = 0; ni < 8; ni++)
                    mma16816(acc[mi][ni], ah[mi], bhf[ni]);
            #pragma unroll
            for (int mi = 0; mi < 2; mi++)
                #pragma unroll
                for (int ni = 0; ni < 8; ni++)
                    mma16816(acc[mi][ni], al[mi], bhf[ni]);
            #pragma unroll
            for (int mi = 0; mi < 2; mi++)
                #pragma unroll
                for (int ni = 0; ni < 8; ni++)
                    mma16816(acc[mi][ni], ah[mi], blf[ni]);
        }
    }

    // ---------- epilogue ----------
    const int g = lane >> 2, tig = lane & 3;
    #pragma unroll
    for (int mi = 0; mi < 2; mi++)
        #pragma unroll
        for (int ni = 0; ni < 8; ni++) {
            int col = wn*64 + ni*8 + tig*2;
            float b0 = sBias[col], b1 = sBias[col + 1];
            #pragma unroll
            for (int half = 0; half < 2; half++) {
                int row = m0 + wm*32 + mi*16 + g + half*8;
                float vx = acc[mi][ni][half*2+0] + b0;
                float vy = acc[mi][ni][half*2+1] + b1;
                if (MODE == 0) {
                    int bb = row >> 10, s = row & 1023;
                    __nv_bfloat16 hx,lx,hy,ly;
                    bf16_split(vx,hx,lx); bf16_split(vy,hy,ly);
                    if (n0 < NQ_) {
                        int h = n0 >> 7;
                        size_t o = ((size_t)((bb*H_ + h)*S_ + s))*DH_ + col;
                        *reinterpret_cast<__nv_bfloat162*>(g_Qh + o) = __nv_bfloat162(hx,hy);
                        *reinterpret_cast<__nv_bfloat162*>(g_Ql + o) = __nv_bfloat162(lx,ly);
                    } else if (n0 < NQ_+NKV_) {
                        int gg = (n0 - NQ_) >> 7;
                        size_t o = ((size_t)((bb*G_ + gg)*S_ + s))*DH_ + col;
                        *reinterpret_cast<__nv_bfloat162*>(g_Kh + o) = __nv_bfloat162(hx,hy);
                        *reinterpret_cast<__nv_bfloat162*>(g_Kl + o) = __nv_bfloat162(lx,ly);
                    } else {
                        int gg = (n0 - NQ_ - NKV_) >> 7;
                        size_t o = ((size_t)(bb*G_ + gg)*DH_ + col)*S_ + s;
                        g_Vth[o] = hx; g_Vtl[o] = lx;
                        g_Vth[o + S_] = hy; g_Vtl[o + S_] = ly;
                    }
                } else {
                    *reinterpret_cast<float2*>(outp + (size_t)row * D_ + n0 + col) =
                        make_float2(vx, vy);
                }
            }
        }
}

// ================= HMMA matryoshka flash attention, split-KV x2 =================
__global__ __launch_bounds__(512, 1)
void attn_mma_kernel()
{
    extern __shared__ char smem[];
    const uint32_t sb = smem_u32(smem);
    const int tid = threadIdx.x, lane = tid & 31, wid = tid >> 5;
    const int qt2 = (S_/QT - 1) - blockIdx.x;
    const int h = blockIdx.y;
    const int zz = blockIdx.z & 1, b = blockIdx.z >> 1;
    const int g = h >> 2;
    const int q0 = qt2 * QT;
    const int ktS = zz * (qt2 + 1);
    const int ktE = ktS + qt2 + 1;
    const int wq = (wid >> 1) * 16;
    const int wk = wid & 1;
    const int barid = 1 + (wid >> 1);
    const int mat = lane >> 3, rin = lane & 7;
    const int gq = lane >> 2, tig = lane & 3;

    const __nv_bfloat16* Khp = g_Kh + ((size_t)(b*G_ + g) * S_) * DH_;
    const __nv_bfloat16* Klp = g_Kl + ((size_t)(b*G_ + g) * S_) * DH_;
    const __nv_bfloat16* Vhp = g_Vth + (size_t)(b*G_ + g) * DH_ * S_;
    const __nv_bfloat16* Vlp = g_Vtl + (size_t)(b*G_ + g) * DH_ * S_;
    const __nv_bfloat16* Qhp = g_Qh + ((size_t)(b*H_ + h) * S_ + q0) * DH_;
    const __nv_bfloat16* Qlp = g_Ql + ((size_t)(b*H_ + h) * S_ + q0) * DH_;

    auto issue_KV = [&](int kt) {
        const uint32_t kst = sb + K_OFF + (uint32_t)(kt & 1) * (2*KTILE);
        const uint32_t vst = sb + V_OFF + (uint32_t)(kt & 1) * (2*VTILE);
        const int k0 = kt * KT;
        #pragma unroll
        for (int i = 0; i < 2; i++) {
            int idx = tid + i * 512;
            { int r = idx >> 4, c = idx & 15;
              cp_async16(kst + swz256(r, c), Khp + (size_t)(k0 + r)*DH_ + c*8);
              cp_async16(kst + KTILE + swz256(r, c), Klp + (size_t)(k0 + r)*DH_ + c*8); }
            { int r = idx >> 3, c = idx & 7;
              cp_async16(vst + swz128(r, c), Vhp + (size_t)r*S_ + k0 + c*8);
              cp_async16(vst + VTILE + swz128(r, c), Vlp + (size_t)r*S_ + k0 + c*8); }
        }
        asm volatile("cp.async.commit_group;" ::: "memory");
    };

    #pragma unroll
    for (int i = 0; i < 4; i++) {
        int idx = tid + i * 512; int r = idx >> 4, c = idx & 15;
        cp_async16(sb + swz256(r, c), Qhp + (size_t)r*DH_ + c*8);
        cp_async16(sb + QTILE + swz256(r, c), Qlp + (size_t)r*DH_ + c*8);
    }
    issue_KV(ktS);

    float o0[2][4] = {}, o1[2][4] = {}, o2[4][4] = {};
    float lsum[3][2] = {};

    const int rq = wq + (mat & 1)*8 + rin;
    const uint32_t qrow_off = (uint32_t)rq * 256;
    const int qsw = rq & 7;
    const uint32_t prow_off = (uint32_t)rq * 128;
    char* pwp = smem + P_OFF;
    float* lred = reinterpret_cast<float*>(smem + P_OFF);

    for (int kt = ktS; kt < ktE; kt++) {
        asm volatile("cp.async.wait_group 0;" ::: "memory");
        __syncthreads();
        if (kt + 1 < ktE) issue_KV(kt + 1);

        const int k0 = kt * KT;
        const uint32_t kst = sb + K_OFF + (uint32_t)(kt & 1) * (2*KTILE);
        const uint32_t vst = sb + V_OFF + (uint32_t)(kt & 1) * (2*VTILE);

        float acc[4][4];
        #pragma unroll
        for (int nb = 0; nb < 4; nb++)
            #pragma unroll
            for (int q = 0; q < 4; q++) acc[nb][q] = 0.f;

        auto qk_steps = [&](int kkA, int kkB) {
            #pragma unroll
            for (int kk = kkA; kk < kkB; kk++) {
                uint32_t qh[4], ql[4];
                uint32_t qoff = qrow_off + (uint32_t)(((kk*2 + (mat>>1)) ^ qsw) << 4);
                ldsm4(qh, sb + qoff);
                ldsm4(ql, sb + QTILE + qoff);
                uint32_t bh[4][2], bl[4][2];
                #pragma unroll
                for (int nb2 = 0; nb2 < 2; nb2++) {
                    int rk = wk*32 + nb2*16 + (mat >> 1)*8 + rin;
                    uint32_t off = swz256(rk, kk*2 + (mat & 1));
                    uint32_t r4[4];
                    ldsm4(r4, kst + off);
                    bh[2*nb2][0] = r4[0]; bh[2*nb2][1] = r4[1];
                    bh[2*nb2+1][0] = r4[2]; bh[2*nb2+1][1] = r4[3];
                    ldsm4(r4, kst + KTILE + off);
                    bl[2*nb2][0] = r4[0]; bl[2*nb2][1] = r4[1];
                    bl[2*nb2+1][0] = r4[2]; bl[2*nb2+1][1] = r4[3];
                }
                // product-major
                #pragma unroll
                for (int nb = 0; nb < 4; nb++) mma16816(acc[nb], qh, bh[nb]);
                #pragma unroll
                for (int nb = 0; nb < 4; nb++) mma16816(acc[nb], qh, bl[nb]);
                #pragma unroll
                for (int nb = 0; nb < 4; nb++) mma16816(acc[nb], ql, bh[nb]);
            }
        };

        auto do_exp = [&](float scale, float* ls) {
            const int r0g = q0 + wq + gq, r1g = r0g + 8;
            const bool need_mask = (k0 + wk*32 + 31 > q0 + wq);
            #pragma unroll
            for (int nb = 0; nb < 4; nb++) {
                int colg = k0 + wk*32 + nb*8 + tig*2;
                float p0 = __expf(acc[nb][0] * scale);
                float p1 = __expf(acc[nb][1] * scale);
                float p2 = __expf(acc[nb][2] * scale);
                float p3 = __expf(acc[nb][3] * scale);
                if (need_mask) {
                    if (colg     > r0g) p0 = 0.f;
                    if (colg + 1 > r0g) p1 = 0.f;
                    if (colg     > r1g) p2 = 0.f;
                    if (colg + 1 > r1g) p3 = 0.f;
                }
                ls[0] += p0 + p1; ls[1] += p2 + p3;
                __nv_bfloat16 h0,l0,h1,l1,h2,l2,h3,l3;
                bf16_split(p0,h0,l0); bf16_split(p1,h1,l1);
                bf16_split(p2,h2,l2); bf16_split(p3,h3,l3);
                int rw0 = wq + gq, rw1 = rw0 + 8;
                int c = wk*4 + nb;
                uint32_t o0b = swz128(rw0, c) + tig*4;
                uint32_t o1b = swz128(rw1, c) + tig*4;
                *reinterpret_cast<__nv_bfloat162*>(pwp + o0b)          = __nv_bfloat162(h0,h1);
                *reinterpret_cast<__nv_bfloat162*>(pwp + o0b + PTILE)  = __nv_bfloat162(l0,l1);
                *reinterpret_cast<__nv_bfloat162*>(pwp + o1b)          = __nv_bfloat162(h2,h3);
                *reinterpret_cast<__nv_bfloat162*>(pwp + o1b + PTILE)  = __nv_bfloat162(l2,l3);
            }
        };

        auto do_pv = [&](int dbase, float (*oacc)[4], int nb2cnt) {
            #pragma unroll
            for (int kk2 = 0; kk2 < 4; kk2++) {
                uint32_t pah[4], pal[4];
                uint32_t poff = prow_off + (uint32_t)(((kk2*2 + (mat>>1)) ^ qsw) << 4);
                ldsm4(pah, sb + P_OFF + poff);
                ldsm4(pal, sb + P_OFF + PTILE + poff);
                uint32_t vh[2][2][2], vl[2][2][2];
                for (int nb2 = 0; nb2 < nb2cnt; nb2++) {
                    int rv = dbase + nb2*16 + (mat >> 1)*8 + rin;
                    uint32_t voff = swz128(rv, kk2*2 + (mat & 1));
                    uint32_t r4[4], s4[4];
                    ldsm4(r4, vst + voff);
                    ldsm4(s4, vst + VTILE + voff);
                    vh[nb2][0][0] = r4[0]; vh[nb2][0][1] = r4[1];
                    vh[nb2][1][0] = r4[2]; vh[nb2][1][1] = r4[3];
                    vl[nb2][0][0] = s4[0]; vl[nb2][0][1] = s4[1];
                    vl[nb2][1][0] = s4[2]; vl[nb2][1][1] = s4[3];
                }
                for (int nb2 = 0; nb2 < nb2cnt; nb2++) {
                    mma16816(oacc[2*nb2],   pah, vh[nb2][0]);
                    mma16816(oacc[2*nb2+1], pah, vh[nb2][1]);
                }
                for (int nb2 = 0; nb2 < nb2cnt; nb2++) {
                    mma16816(oacc[2*nb2],   pah, vl[nb2][0]);
                    mma16816(oacc[2*nb2+1], pah, vl[nb2][1]);
                }
                for (int nb2 = 0; nb2 < nb2cnt; nb2++) {
                    mma16816(oacc[2*nb2],   pal, vh[nb2][0]);
                    mma16816(oacc[2*nb2+1], pal, vh[nb2][1]);
                }
            }
        };

        qk_steps(0, 2);
        do_exp(SCALE0, lsum[0]);
        bar_pair(barid);
        do_pv(0 + wk*16, o0, 1);
        qk_steps(2, 4);
        bar_pair(barid);
        do_exp(SCALE1, lsum[1]);
        bar_pair(barid);
        do_pv(32 + wk*16, o1, 1);
        qk_steps(4, 8);
        bar_pair(barid);
        do_exp(SCALE2, lsum[2]);
        bar_pair(barid);
        do_pv(64 + wk*32, o2, 2);
    }

    #pragma unroll
    for (int L = 0; L < 3; L++)
        #pragma unroll
        for (int j = 0; j < 2; j++) {
            lsum[L][j] += __shfl_xor_sync(0xffffffffu, lsum[L][j], 1);
            lsum[L][j] += __shfl_xor_sync(0xffffffffu, lsum[L][j], 2);
        }
    __syncthreads();
    if (tig == 0) {
        #pragma unroll
        for (int L = 0; L < 3; L++) {
            lred[L*256 + (wq + gq)*2 + wk]     = lsum[L][0];
            lred[L*256 + (wq + gq + 8)*2 + wk] = lsum[L][1];
        }
    }
    __syncthreads();

    const int r0 = wq + gq, r1 = r0 + 8;

    if (wk == 0 && tig == 0) {
        int idx0 = (b*H_ + h)*S_ + q0 + r0;
        int idx1 = idx0 + 8;
        #pragma unroll
        for (int L = 0; L < 3; L++) {
            g_lsum[(zz*3 + L)*BHS_ + idx0] = lred[L*256 + r0*2] + lred[L*256 + r0*2 + 1];
            g_lsum[(zz*3 + L)*BHS_ + idx1] = lred[L*256 + r1*2] + lred[L*256 + r1*2 + 1];
        }
    }

    float* part = g_part + (size_t)zz * PZ_;
    size_t base0 = ((size_t)(b*S_ + q0 + r0)) * D_ + (size_t)h * DH_;
    size_t base1 = ((size_t)(b*S_ + q0 + r1)) * D_ + (size_t)h * DH_;
    #pragma unroll
    for (int j = 0; j < 2; j++) {
        int d = wk*16 + j*8 + tig*2;
        *reinterpret_cast<float2*>(part + base0 + d)      = make_float2(o0[j][0], o0[j][1]);
        *reinterpret_cast<float2*>(part + base1 + d)      = make_float2(o0[j][2], o0[j][3]);
        *reinterpret_cast<float2*>(part + base0 + 32 + d) = make_float2(o1[j][0], o1[j][1]);
        *reinterpret_cast<float2*>(part + base1 + 32 + d) = make_float2(o1[j][2], o1[j][3]);
    }
    #pragma unroll
    for (int j = 0; j < 4; j++) {
        int d = 64 + wk*32 + j*8 + tig*2;
        *reinterpret_cast<float2*>(part + base0 + d) = make_float2(o2[j][0], o2[j][1]);
        *reinterpret_cast<float2*>(part + base1 + d) = make_float2(o2[j][2], o2[j][3]);
    }
}

// ================= attention combine =================
__global__ __launch_bounds__(256)
void attn_combine()
{
    const int m = blockIdx.x;
    const int col = blockIdx.y * 512 + threadIdx.x * 2;
    float2 p0 = *reinterpret_cast<const float2*>(g_part + (size_t)m*D_ + col);
    float2 p1 = *reinterpret_cast<const float2*>(g_part + PZ_ + (size_t)m*D_ + col);
    const int h = col >> 7, d = col & 127;
    const int L = (d < 32) ? 0 : (d < 64) ? 1 : 2;
    const int b = m >> 10, s = m & 1023;
    const int idx = (b*H_ + h)*S_ + s;
    float ls = g_lsum[L*BHS_ + idx] + g_lsum[(3 + L)*BHS_ + idx];
    float inv = 1.f / ls;
    float v0 = (p0.x + p1.x) * inv;
    float v1 = (p0.y + p1.y) * inv;
    __nv_bfloat16 h0,l0,h1,l1;
    bf16_split(v0,h0,l0); bf16_split(v1,h1,l1);
    size_t o = (size_t)m * D_ + col;
    *reinterpret_cast<__nv_bfloat162*>(g_AOh + o) = __nv_bfloat162(h0,h1);
    *reinterpret_cast<__nv_bfloat162*>(g_AOl + o) = __nv_bfloat162(l0,l1);
}

// ================= launch =================
extern "C" void kernel_launch(void* const* d_in, const int* in_sizes, int n_in,
                              void* d_out, int out_size)
{
    (void)in_sizes; (void)n_in; (void)out_size;
    const float* x  = (const float*)d_in[0];
    const float* Wq = (const float*)d_in[2];
    const float* bq = (const float*)d_in[3];
    const float* Wk = (const float*)d_in[4];
    const float* bk = (const float*)d_in[5];
    const float* Wv = (const float*)d_in[6];
    const float* bv = (const float*)d_in[7];
    const float* Wo = (const float*)d_in[8];
    const float* bo = (const float*)d_in[9];
    float* out = (float*)d_out;

    convx_kernel<<<MROWS_*D_/4/256, 256>>>(x);
    tconv_qkv_kernel<<<dim3(NTOT_/64, D_/64), 256>>>(Wq, Wk, Wv);
    tconv_wo_kernel<<<dim3(D_/64, D_/64), 256>>>(Wo);

    static __nv_bfloat16 *pxh = nullptr, *pxl, *pwth, *pwtl, *pwoth, *pwotl, *paoh, *paol;
    if (!pxh) {
        cudaGetSymbolAddress((void**)&pxh, g_xh);
        cudaGetSymbolAddress((void**)&pxl, g_xl);
        cudaGetSymbolAddress((void**)&pwth, g_Wth);
        cudaGetSymbolAddress((void**)&pwtl, g_Wtl);
        cudaGetSymbolAddress((void**)&pwoth, g_Woth);
        cudaGetSymbolAddress((void**)&pwotl, g_Wotl);
        cudaGetSymbolAddress((void**)&paoh, g_AOh);
        cudaGetSymbolAddress((void**)&paol, g_AOl);
    }

    static bool attr_set = false;
    if (!attr_set) {
        cudaFuncSetAttribute(gemm_mma_kernel<0>, cudaFuncAttributeMaxDynamicSharedMemorySize, GEMM_SMEM);
        cudaFuncSetAttribute(gemm_mma_kernel<1>, cudaFuncAttributeMaxDynamicSharedMemorySize, GEMM_SMEM);
        cudaFuncSetAttribute(attn_mma_kernel, cudaFuncAttributeMaxDynamicSharedMemorySize, ATT_SMEM);
        attr_set = true;
    }

    gemm_mma_kernel<0><<<dim3(NTOT_/128, MROWS_/128), 256, GEMM_SMEM>>>(
        pxh, pxl, pwth, pwtl, nullptr, bq, bk, bv);

    attn_mma_kernel<<<dim3(S_/QT, H_, B_*2), 512, ATT_SMEM>>>();
    attn_combine<<<dim3(MROWS_, 4), 256>>>();

    gemm_mma_kernel<1><<<dim3(D_/128, MROWS_/128), 256, GEMM_SMEM>>>(
        paoh, paol, pwoth, pwotl, out, bo, nullptr, nullptr);
}

// round 13
// speedup vs baseline: 1.3546x; 1.3479x over previous
#include <cuda_runtime.h>
#include <cuda_fp16.h>
#include <stdint.h>
#include <cstdint>
#include <math.h>

#define B_ 2
#define S_ 1024
#define D_ 2048
#define H_ 16
#define G_ 4
#define DH_ 128
#define NQ_ 2048
#define NKV_ 512
#define NTOT_ 3072
#define MROWS_ 2048
#define PZ_ (2048*3072)
#define BHS_ (B_*H_*S_)

// GEMM: A hi/lo + B single, KC=32, pitch 64 swizzled, 3 stages
#define KC 32
#define TILE_GB 8192
#define STAGE_GB (3 * TILE_GB)          // Ah, Al, B
#define GEMM_SMEM (3 * STAGE_GB + 512)  // 74240

// Attention (Q hi/lo, K single, V single, P hi/lo)
#define QT 128
#define KT 64
#define QTILE 32768
#define KTILE 16384
#define VTILE 16384
#define PTILE 16384
#define K_OFF 65536
#define V_OFF  98304
#define P_OFF 131072
#define ATT_SMEM 163840

#define SCALE0 0.17677669529663687f
#define SCALE1 0.125f
#define SCALE2 0.08838834764831843f

// ---------------- device scratch ----------------
__device__ float g_part[2*2048*3072];
__device__ float g_lsum[2*3*BHS_];
__device__ __half g_xh[MROWS_*D_];
__device__ __half g_xl[MROWS_*D_];
__device__ __half g_Wt[NTOT_*D_];      // W_qkv^T, perm folded, single fp16
__device__ __half g_Wot[D_*D_];        // Wo^T row-perm folded, single fp16
__device__ __half g_AOh[MROWS_*D_];
__device__ __half g_AOl[MROWS_*D_];
__device__ __half g_Qh[B_*H_*S_*DH_];
__device__ __half g_Ql[B_*H_*S_*DH_];
__device__ __half g_K [B_*G_*S_*DH_];  // single fp16
__device__ __half g_Vt[B_*G_*DH_*S_];  // single fp16, [b,g,d,s]

// ---------------- matryoshka reorder ----------------
__device__ __forceinline__ int perm16(int h, int d) {
    return (d < 32) ? (h*32 + d)
         : (d < 64) ? (512 + h*32 + (d-32))
                    : (1024 + h*64 + (d-64));
}
__device__ __forceinline__ int perm4(int g, int d) {
    return (d < 32) ? (g*32 + d)
         : (d < 64) ? (128 + g*32 + (d-32))
                    : (256 + g*64 + (d-64));
}

// ---------------- PTX helpers ----------------
__device__ __forceinline__ uint32_t smem_u32(const void* p) {
    uint32_t a;
    asm("{ .reg .u64 t; cvta.to.shared.u64 t, %1; cvt.u32.u64 %0, t; }" : "=r"(a) : "l"(p));
    return a;
}
__device__ __forceinline__ void cp_async16(uint32_t d, const void* g) {
    asm volatile("cp.async.cg.shared.global [%0], [%1], 16;" :: "r"(d), "l"(g));
}
__device__ __forceinline__ void ldsm4(uint32_t* r, uint32_t addr) {
    asm volatile("ldmatrix.sync.aligned.m8n8.x4.shared.b16 {%0,%1,%2,%3}, [%4];"
                 : "=r"(r[0]), "=r"(r[1]), "=r"(r[2]), "=r"(r[3]) : "r"(addr));
}
__device__ __forceinline__ void mma16816(float* c, const uint32_t* a, const uint32_t* b) {
    asm volatile(
        "mma.sync.aligned.m16n8k16.row.col.f32.f16.f16.f32 "
        "{%0,%1,%2,%3}, {%4,%5,%6,%7}, {%8,%9}, {%0,%1,%2,%3};"
        : "+f"(c[0]), "+f"(c[1]), "+f"(c[2]), "+f"(c[3])
        : "r"(a[0]), "r"(a[1]), "r"(a[2]), "r"(a[3]), "r"(b[0]), "r"(b[1]));
}
__device__ __forceinline__ void bar_pair(int id) {
    asm volatile("bar.sync %0, 64;" :: "r"(id) : "memory");
}
__device__ __forceinline__ void f16_split(float v, __half& h, __half& l) {
    h = __float2half(v);
    l = __float2half(v - __half2float(h));
}
__device__ __forceinline__ uint32_t swz64(int r, int c)  { return (uint32_t)r*64  + (uint32_t)((c ^ ((r>>1)&3)) << 4); }
__device__ __forceinline__ uint32_t swz128(int r, int c) { return (uint32_t)r*128 + (uint32_t)((c ^ (r&7)) << 4); }
__device__ __forceinline__ uint32_t swz256(int r, int c) { return (uint32_t)r*256 + (uint32_t)((c ^ (r&7)) << 4); }

// ================= converters =================
__global__ __launch_bounds__(256) void convx_kernel(const float* __restrict__ x) {
    int i = blockIdx.x * 256 + threadIdx.x;
    float4 v = reinterpret_cast<const float4*>(x)[i];
    __half h0,l0,h1,l1,h2,l2,h3,l3;
    f16_split(v.x,h0,l0); f16_split(v.y,h1,l1); f16_split(v.z,h2,l2); f16_split(v.w,h3,l3);
    __half2* ph = reinterpret_cast<__half2*>(g_xh);
    __half2* pl = reinterpret_cast<__half2*>(g_xl);
    ph[2*i]   = __half2(h0,h1); ph[2*i+1] = __half2(h2,h3);
    pl[2*i]   = __half2(l0,l1); pl[2*i+1] = __half2(l2,l3);
}

__global__ __launch_bounds__(256)
void tconv_qkv_kernel(const float* __restrict__ Wq, const float* __restrict__ Wk,
                      const float* __restrict__ Wv) {
    __shared__ float ts[64][65];
    const int tid = threadIdx.x;
    const int n0 = blockIdx.x * 64, k0 = blockIdx.y * 64;
    for (int idx = tid; idx < 4096; idx += 256) {
        int kk = idx >> 6, nn = idx & 63;
        int n = n0 + nn;
        const float* W; int ldw, src;
        if (n < NQ_)            { W = Wq; ldw = NQ_;  src = perm16(n >> 7, n & 127); }
        else if (n < NQ_+NKV_)  { int t = n - NQ_;        W = Wk; ldw = NKV_; src = perm4(t >> 7, t & 127); }
        else                    { int t = n - NQ_ - NKV_; W = Wv; ldw = NKV_; src = perm4(t >> 7, t & 127); }
        ts[kk][nn] = W[(size_t)(k0 + kk) * ldw + src];
    }
    __syncthreads();
    for (int idx = tid; idx < 4096; idx += 256) {
        int nn = idx >> 6, kk = idx & 63;
        g_Wt[(size_t)(n0 + nn) * D_ + k0 + kk] = __float2half(ts[kk][nn]);
    }
}

__global__ __launch_bounds__(256)
void tconv_wo_kernel(const float* __restrict__ Wo) {
    __shared__ float ts[64][65];
    const int tid = threadIdx.x;
    const int n0 = blockIdx.x * 64, k0 = blockIdx.y * 64;
    for (int idx = tid; idx < 4096; idx += 256) {
        int kk = idx >> 6, nn = idx & 63;
        int k = k0 + kk;
        int srcrow = perm16(k >> 7, k & 127);
        ts[kk][nn] = Wo[(size_t)srcrow * D_ + n0 + nn];
    }
    __syncthreads();
    for (int idx = tid; idx < 4096; idx += 256) {
        int nn = idx >> 6, kk = idx & 63;
        g_Wot[(size_t)(n0 + nn) * D_ + k0 + kk] = __float2half(ts[kk][nn]);
    }
}

// ================= fp16 2-product GEMM (A hi/lo, B single) =================
template<int MODE>
__global__ __launch_bounds__(256, 2)
void gemm_mma_kernel(const __half* __restrict__ Ah, const __half* __restrict__ Al,
                     const __half* __restrict__ Bs,
                     float* __restrict__ outp,
                     const float* __restrict__ bq, const float* __restrict__ bk,
                     const float* __restrict__ bv)
{
    extern __shared__ char smem[];
    const uint32_t sb = smem_u32(smem);
    float* sBias = reinterpret_cast<float*>(smem + 3 * STAGE_GB);

    const int tid  = threadIdx.x;
    const int lane = tid & 31;
    const int wid  = tid >> 5;
    const int wm = wid >> 1;
    const int wn = wid & 1;
    const int n0 = blockIdx.x * 128;
    const int m0 = blockIdx.y * 128;
    const int NK = D_ / KC;

    if (tid < 128) {
        int n = n0 + tid;
        float b;
        if (MODE == 0) {
            if (n < NQ_)            b = bq[perm16(n >> 7, n & 127)];
            else if (n < NQ_+NKV_)  { int t = n - NQ_;        b = bk[perm4(t >> 7, t & 127)]; }
            else                    { int t = n - NQ_ - NKV_; b = bv[perm4(t >> 7, t & 127)]; }
        } else b = bq[n];
        sBias[tid] = b;
    }

    const __half* srcs[3] = {
        Ah + (size_t)m0 * D_, Al + (size_t)m0 * D_, Bs + (size_t)n0 * D_ };

    auto load_stage = [&](int chunk) {
        const uint32_t st = sb + (uint32_t)(chunk % 3) * STAGE_GB;
        const int k0 = chunk * KC;
        #pragma unroll
        for (int t = 0; t < 3; t++) {
            const __half* s = srcs[t];
            const uint32_t tb = st + t * TILE_GB;
            #pragma unroll
            for (int it = 0; it < 2; it++) {
                int idx = tid + it * 256;
                int r = idx >> 2, c = idx & 3;
                cp_async16(tb + swz64(r, c), s + (size_t)r * D_ + k0 + c * 8);
            }
        }
        asm volatile("cp.async.commit_group;" ::: "memory");
    };

    float acc[2][8][4];
    #pragma unroll
    for (int mi = 0; mi < 2; mi++)
        #pragma unroll
        for (int ni = 0; ni < 8; ni++)
            #pragma unroll
            for (int q = 0; q < 4; q++) acc[mi][ni][q] = 0.f;

    const int mat = lane >> 3, rin = lane & 7;
    const int arow = wm*32 + (mat & 1)*8 + rin;
    const int acb  = (mat >> 1);
    const int brow = wn*64 + (mat >> 1)*8 + rin;
    const int bcb  = (mat & 1);

    load_stage(0);
    load_stage(1);

    for (int i = 0; i < NK; i++) {
        if (i >= NK - 1) asm volatile("cp.async.wait_group 0;" ::: "memory");
        else             asm volatile("cp.async.wait_group 1;" ::: "memory");
        __syncthreads();
        if (i + 2 < NK) load_stage(i + 2);

        const uint32_t st = sb + (uint32_t)(i % 3) * STAGE_GB;
        const uint32_t aH = st, aL = st + TILE_GB, bB = st + 2*TILE_GB;

        #pragma unroll
        for (int kk = 0; kk < 2; kk++) {
            uint32_t ah[2][4], al[2][4];
            #pragma unroll
            for (int mi = 0; mi < 2; mi++) {
                int r = arow + mi*16;
                uint32_t off = swz64(r, kk*2 + acb);
                ldsm4(ah[mi], aH + off);
                ldsm4(al[mi], aL + off);
            }
            uint32_t bf[8][2];
            #pragma unroll
            for (int nb2 = 0; nb2 < 4; nb2++) {
                int r = brow + nb2*16;
                uint32_t off = swz64(r, kk*2 + bcb);
                uint32_t r4[4];
                ldsm4(r4, bB + off);
                bf[2*nb2][0] = r4[0]; bf[2*nb2][1] = r4[1];
                bf[2*nb2+1][0] = r4[2]; bf[2*nb2+1][1] = r4[3];
            }
            #pragma unroll
            for (int mi = 0; mi < 2; mi++)
                #pragma unroll
                for (int ni = 0; ni < 8; ni++)
                    mma16816(acc[mi][ni], ah[mi], bf[ni]);
            #pragma unroll
            for (int mi = 0; mi < 2; mi++)
                #pragma unroll
                for (int ni = 0; ni < 8; ni++)
                    mma16816(acc[mi][ni], al[mi], bf[ni]);
        }
    }

    // ---------- epilogue ----------
    const int g = lane >> 2, tig = lane & 3;
    #pragma unroll
    for (int mi = 0; mi < 2; mi++)
        #pragma unroll
        for (int ni = 0; ni < 8; ni++) {
            int col = wn*64 + ni*8 + tig*2;
            float b0 = sBias[col], b1 = sBias[col + 1];
            #pragma unroll
            for (int half = 0; half < 2; half++) {
                int row = m0 + wm*32 + mi*16 + g + half*8;
                float vx = acc[mi][ni][half*2+0] + b0;
                float vy = acc[mi][ni][half*2+1] + b1;
                if (MODE == 0) {
                    int bb = row >> 10, s = row & 1023;
                    if (n0 < NQ_) {
                        int h = n0 >> 7;
                        __half hx,lx,hy,ly;
                        f16_split(vx,hx,lx); f16_split(vy,hy,ly);
                        size_t o = ((size_t)((bb*H_ + h)*S_ + s))*DH_ + col;
                        *reinterpret_cast<__half2*>(g_Qh + o) = __half2(hx,hy);
                        *reinterpret_cast<__half2*>(g_Ql + o) = __half2(lx,ly);
                    } else if (n0 < NQ_+NKV_) {
                        int gg = (n0 - NQ_) >> 7;
                        size_t o = ((size_t)((bb*G_ + gg)*S_ + s))*DH_ + col;
                        *reinterpret_cast<__half2*>(g_K + o) =
                            __half2(__float2half(vx), __float2half(vy));
                    } else {
                        int gg = (n0 - NQ_ - NKV_) >> 7;
                        size_t o = ((size_t)(bb*G_ + gg)*DH_ + col)*S_ + s;
                        g_Vt[o]      = __float2half(vx);
                        g_Vt[o + S_] = __float2half(vy);
                    }
                } else {
                    *reinterpret_cast<float2*>(outp + (size_t)row * D_ + n0 + col) =
                        make_float2(vx, vy);
                }
            }
        }
}

// ================= fp16 flash attention, split-KV x2 =================
__global__ __launch_bounds__(512, 1)
void attn_mma_kernel()
{
    extern __shared__ char smem[];
    const uint32_t sb = smem_u32(smem);
    const int tid = threadIdx.x, lane = tid & 31, wid = tid >> 5;
    const int qt2 = (S_/QT - 1) - blockIdx.x;
    const int h = blockIdx.y;
    const int zz = blockIdx.z & 1, b = blockIdx.z >> 1;
    const int g = h >> 2;
    const int q0 = qt2 * QT;
    const int ktS = zz * (qt2 + 1);
    const int ktE = ktS + qt2 + 1;
    const int wq = (wid >> 1) * 16;
    const int wk = wid & 1;
    const int barid = 1 + (wid >> 1);
    const int mat = lane >> 3, rin = lane & 7;
    const int gq = lane >> 2, tig = lane & 3;

    const __half* Kp  = g_K  + ((size_t)(b*G_ + g) * S_) * DH_;
    const __half* Vp  = g_Vt + (size_t)(b*G_ + g) * DH_ * S_;
    const __half* Qhp = g_Qh + ((size_t)(b*H_ + h) * S_ + q0) * DH_;
    const __half* Qlp = g_Ql + ((size_t)(b*H_ + h) * S_ + q0) * DH_;

    auto issue_KV = [&](int kt) {
        const uint32_t kst = sb + K_OFF + (uint32_t)(kt & 1) * KTILE;
        const uint32_t vst = sb + V_OFF + (uint32_t)(kt & 1) * VTILE;
        const int k0 = kt * KT;
        #pragma unroll
        for (int i = 0; i < 2; i++) {
            int idx = tid + i * 512;
            { int r = idx >> 4, c = idx & 15;
              cp_async16(kst + swz256(r, c), Kp + (size_t)(k0 + r)*DH_ + c*8); }
            { int r = idx >> 3, c = idx & 7;
              cp_async16(vst + swz128(r, c), Vp + (size_t)r*S_ + k0 + c*8); }
        }
        asm volatile("cp.async.commit_group;" ::: "memory");
    };

    #pragma unroll
    for (int i = 0; i < 4; i++) {
        int idx = tid + i * 512; int r = idx >> 4, c = idx & 15;
        cp_async16(sb + swz256(r, c), Qhp + (size_t)r*DH_ + c*8);
        cp_async16(sb + QTILE + swz256(r, c), Qlp + (size_t)r*DH_ + c*8);
    }
    issue_KV(ktS);

    float o0[2][4] = {}, o1[2][4] = {}, o2[4][4] = {};
    float lsum[3][2] = {};

    const int rq = wq + (mat & 1)*8 + rin;
    const uint32_t qrow_off = (uint32_t)rq * 256;
    const int qsw = rq & 7;
    const uint32_t prow_off = (uint32_t)rq * 128;
    char* pwp = smem + P_OFF;
    float* lred = reinterpret_cast<float*>(smem + P_OFF);

    for (int kt = ktS; kt < ktE; kt++) {
        asm volatile("cp.async.wait_group 0;" ::: "memory");
        __syncthreads();
        if (kt + 1 < ktE) issue_KV(kt + 1);

        const int k0 = kt * KT;
        const uint32_t kst = sb + K_OFF + (uint32_t)(kt & 1) * KTILE;
        const uint32_t vst = sb + V_OFF + (uint32_t)(kt & 1) * VTILE;

        float acc[4][4];
        #pragma unroll
        for (int nb = 0; nb < 4; nb++)
            #pragma unroll
            for (int q = 0; q < 4; q++) acc[nb][q] = 0.f;

        auto qk_steps = [&](int kkA, int kkB) {
            #pragma unroll
            for (int kk = kkA; kk < kkB; kk++) {
                uint32_t qh[4], ql[4];
                uint32_t qoff = qrow_off + (uint32_t)(((kk*2 + (mat>>1)) ^ qsw) << 4);
                ldsm4(qh, sb + qoff);
                ldsm4(ql, sb + QTILE + qoff);
                uint32_t bh[4][2];
                #pragma unroll
                for (int nb2 = 0; nb2 < 2; nb2++) {
                    int rk = wk*32 + nb2*16 + (mat >> 1)*8 + rin;
                    uint32_t off = swz256(rk, kk*2 + (mat & 1));
                    uint32_t r4[4];
                    ldsm4(r4, kst + off);
                    bh[2*nb2][0] = r4[0]; bh[2*nb2][1] = r4[1];
                    bh[2*nb2+1][0] = r4[2]; bh[2*nb2+1][1] = r4[3];
                }
                #pragma unroll
                for (int nb = 0; nb < 4; nb++) mma16816(acc[nb], qh, bh[nb]);
                #pragma unroll
                for (int nb = 0; nb < 4; nb++) mma16816(acc[nb], ql, bh[nb]);
            }
        };

        auto do_exp = [&](float scale, float* ls) {
            const int r0g = q0 + wq + gq, r1g = r0g + 8;
            const bool need_mask = (k0 + wk*32 + 31 > q0 + wq);
            #pragma unroll
            for (int nb = 0; nb < 4; nb++) {
                int colg = k0 + wk*32 + nb*8 + tig*2;
                float p0 = __expf(acc[nb][0] * scale);
                float p1 = __expf(acc[nb][1] * scale);
                float p2 = __expf(acc[nb][2] * scale);
                float p3 = __expf(acc[nb][3] * scale);
                if (need_mask) {
                    if (colg     > r0g) p0 = 0.f;
                    if (colg + 1 > r0g) p1 = 0.f;
                    if (colg     > r1g) p2 = 0.f;
                    if (colg + 1 > r1g) p3 = 0.f;
                }
                ls[0] += p0 + p1; ls[1] += p2 + p3;
                __half h0,l0,h1,l1,h2,l2,h3,l3;
                f16_split(p0,h0,l0); f16_split(p1,h1,l1);
                f16_split(p2,h2,l2); f16_split(p3,h3,l3);
                int rw0 = wq + gq, rw1 = rw0 + 8;
                int c = wk*4 + nb;
                uint32_t o0b = swz128(rw0, c) + tig*4;
                uint32_t o1b = swz128(rw1, c) + tig*4;
                *reinterpret_cast<__half2*>(pwp + o0b)          = __half2(h0,h1);
                *reinterpret_cast<__half2*>(pwp + o0b + PTILE)  = __half2(l0,l1);
                *reinterpret_cast<__half2*>(pwp + o1b)          = __half2(h2,h3);
                *reinterpret_cast<__half2*>(pwp + o1b + PTILE)  = __half2(l2,l3);
            }
        };

        auto do_pv = [&](int dbase, float (*oacc)[4], int nb2cnt) {
            #pragma unroll
            for (int kk2 = 0; kk2 < 4; kk2++) {
                uint32_t pah[4], pal[4];
                uint32_t poff = prow_off + (uint32_t)(((kk2*2 + (mat>>1)) ^ qsw) << 4);
                ldsm4(pah, sb + P_OFF + poff);
                ldsm4(pal, sb + P_OFF + PTILE + poff);
                uint32_t vh[2][2][2];
                for (int nb2 = 0; nb2 < nb2cnt; nb2++) {
                    int rv = dbase + nb2*16 + (mat >> 1)*8 + rin;
                    uint32_t voff = swz128(rv, kk2*2 + (mat & 1));
                    uint32_t r4[4];
                    ldsm4(r4, vst + voff);
                    vh[nb2][0][0] = r4[0]; vh[nb2][0][1] = r4[1];
                    vh[nb2][1][0] = r4[2]; vh[nb2][1][1] = r4[3];
                }
                for (int nb2 = 0; nb2 < nb2cnt; nb2++) {
                    mma16816(oacc[2*nb2],   pah, vh[nb2][0]);
                    mma16816(oacc[2*nb2+1], pah, vh[nb2][1]);
                }
                for (int nb2 = 0; nb2 < nb2cnt; nb2++) {
                    mma16816(oacc[2*nb2],   pal, vh[nb2][0]);
                    mma16816(oacc[2*nb2+1], pal, vh[nb2][1]);
                }
            }
        };

        qk_steps(0, 2);
        do_exp(SCALE0, lsum[0]);
        bar_pair(barid);
        do_pv(0 + wk*16, o0, 1);
        qk_steps(2, 4);
        bar_pair(barid);
        do_exp(SCALE1, lsum[1]);
        bar_pair(barid);
        do_pv(32 + wk*16, o1, 1);
        qk_steps(4, 8);
        bar_pair(barid);
        do_exp(SCALE2, lsum[2]);
        bar_pair(barid);
        do_pv(64 + wk*32, o2, 2);
    }

    #pragma unroll
    for (int L = 0; L < 3; L++)
        #pragma unroll
        for (int j = 0; j < 2; j++) {
            lsum[L][j] += __shfl_xor_sync(0xffffffffu, lsum[L][j], 1);
            lsum[L][j] += __shfl_xor_sync(0xffffffffu, lsum[L][j], 2);
        }
    __syncthreads();
    if (tig == 0) {
        #pragma unroll
        for (int L = 0; L < 3; L++) {
            lred[L*256 + (wq + gq)*2 + wk]     = lsum[L][0];
            lred[L*256 + (wq + gq + 8)*2 + wk] = lsum[L][1];
        }
    }
    __syncthreads();

    const int r0 = wq + gq, r1 = r0 + 8;

    if (wk == 0 && tig == 0) {
        int idx0 = (b*H_ + h)*S_ + q0 + r0;
        int idx1 = idx0 + 8;
        #pragma unroll
        for (int L = 0; L < 3; L++) {
            g_lsum[(zz*3 + L)*BHS_ + idx0] = lred[L*256 + r0*2] + lred[L*256 + r0*2 + 1];
            g_lsum[(zz*3 + L)*BHS_ + idx1] = lred[L*256 + r1*2] + lred[L*256 + r1*2 + 1];
        }
    }

    float* part = g_part + (size_t)zz * PZ_;
    size_t base0 = ((size_t)(b*S_ + q0 + r0)) * D_ + (size_t)h * DH_;
    size_t base1 = ((size_t)(b*S_ + q0 + r1)) * D_ + (size_t)h * DH_;
    #pragma unroll
    for (int j = 0; j < 2; j++) {
        int d = wk*16 + j*8 + tig*2;
        *reinterpret_cast<float2*>(part + base0 + d)      = make_float2(o0[j][0], o0[j][1]);
        *reinterpret_cast<float2*>(part + base1 + d)      = make_float2(o0[j][2], o0[j][3]);
        *reinterpret_cast<float2*>(part + base0 + 32 + d) = make_float2(o1[j][0], o1[j][1]);
        *reinterpret_cast<float2*>(part + base1 + 32 + d) = make_float2(o1[j][2], o1[j][3]);
    }
    #pragma unroll
    for (int j = 0; j < 4; j++) {
        int d = 64 + wk*32 + j*8 + tig*2;
        *reinterpret_cast<float2*>(part + base0 + d) = make_float2(o2[j][0], o2[j][1]);
        *reinterpret_cast<float2*>(part + base1 + d) = make_float2(o2[j][2], o2[j][3]);
    }
}

// ================= attention combine =================
__global__ __launch_bounds__(256)
void attn_combine()
{
    const int m = blockIdx.x;
    const int col = blockIdx.y * 512 + threadIdx.x * 2;
    float2 p0 = *reinterpret_cast<const float2*>(g_part + (size_t)m*D_ + col);
    float2 p1 = *reinterpret_cast<const float2*>(g_part + PZ_ + (size_t)m*D_ + col);
    const int h = col >> 7, d = col & 127;
    const int L = (d < 32) ? 0 : (d < 64) ? 1 : 2;
    const int b = m >> 10, s = m & 1023;
    const int idx = (b*H_ + h)*S_ + s;
    float ls = g_lsum[L*BHS_ + idx] + g_lsum[(3 + L)*BHS_ + idx];
    float inv = 1.f / ls;
    float v0 = (p0.x + p1.x) * inv;
    float v1 = (p0.y + p1.y) * inv;
    __half h0,l0,h1,l1;
    f16_split(v0,h0,l0); f16_split(v1,h1,l1);
    size_t o = (size_t)m * D_ + col;
    *reinterpret_cast<__half2*>(g_AOh + o) = __half2(h0,h1);
    *reinterpret_cast<__half2*>(g_AOl + o) = __half2(l0,l1);
}

// ================= launch =================
extern "C" void kernel_launch(void* const* d_in, const int* in_sizes, int n_in,
                              void* d_out, int out_size)
{
    (void)in_sizes; (void)n_in; (void)out_size;
    const float* x  = (const float*)d_in[0];
    const float* Wq = (const float*)d_in[2];
    const float* bq = (const float*)d_in[3];
    const float* Wk = (const float*)d_in[4];
    const float* bk = (const float*)d_in[5];
    const float* Wv = (const float*)d_in[6];
    const float* bv = (const float*)d_in[7];
    const float* Wo = (const float*)d_in[8];
    const float* bo = (const float*)d_in[9];
    float* out = (float*)d_out;

    convx_kernel<<<MROWS_*D_/4/256, 256>>>(x);
    tconv_qkv_kernel<<<dim3(NTOT_/64, D_/64), 256>>>(Wq, Wk, Wv);
    tconv_wo_kernel<<<dim3(D_/64, D_/64), 256>>>(Wo);

    static __half *pxh = nullptr, *pxl, *pwt, *pwot, *paoh, *paol;
    if (!pxh) {
        cudaGetSymbolAddress((void**)&pxh, g_xh);
        cudaGetSymbolAddress((void**)&pxl, g_xl);
        cudaGetSymbolAddress((void**)&pwt, g_Wt);
        cudaGetSymbolAddress((void**)&pwot, g_Wot);
        cudaGetSymbolAddress((void**)&paoh, g_AOh);
        cudaGetSymbolAddress((void**)&paol, g_AOl);
    }

    static bool attr_set = false;
    if (!attr_set) {
        cudaFuncSetAttribute(gemm_mma_kernel<0>, cudaFuncAttributeMaxDynamicSharedMemorySize, GEMM_SMEM);
        cudaFuncSetAttribute(gemm_mma_kernel<1>, cudaFuncAttributeMaxDynamicSharedMemorySize, GEMM_SMEM);
        cudaFuncSetAttribute(attn_mma_kernel, cudaFuncAttributeMaxDynamicSharedMemorySize, ATT_SMEM);
        attr_set = true;
    }

    gemm_mma_kernel<0><<<dim3(NTOT_/128, MROWS_/128), 256, GEMM_SMEM>>>(
        pxh, pxl, pwt, nullptr, bq, bk, bv);

    attn_mma_kernel<<<dim3(S_/QT, H_, B_*2), 512, ATT_SMEM>>>();
    attn_combine<<<dim3(MROWS_, 4), 256>>>();

    gemm_mma_kernel<1><<<dim3(D_/128, MROWS_/128), 256, GEMM_SMEM>>>(
        paoh, paol, pwot, out, bo, nullptr, nullptr);
}

// round 14
// speedup vs baseline: 1.5859x; 1.1707x over previous
#include <cuda_runtime.h>
#include <cuda_fp16.h>
#include <stdint.h>
#include <cstdint>
#include <math.h>

#define B_ 2
#define S_ 1024
#define D_ 2048
#define H_ 16
#define G_ 4
#define DH_ 128
#define NQ_ 2048
#define NKV_ 512
#define NTOT_ 3072
#define MROWS_ 2048
#define PZ_ (2048*3072)
#define BHS_ (B_*H_*S_)

// QKV GEMM: A hi/lo + B single, KC=32, pitch 64 swizzled, 3 stages
#define KC 32
#define TILE_GB 8192
#define STAGE_GB (3 * TILE_GB)
#define GEMM_SMEM (3 * STAGE_GB + 512)

// out GEMM: A single + B single, 1 product
#define STAGE_OB (2 * TILE_GB)
#define GEMM_O_SMEM (3 * STAGE_OB + 512)

// Attention (Q hi/lo, K single, V single, P single)
#define QT 128
#define KT 64
#define QTILE 32768
#define KTILE 16384
#define VTILE 16384
#define PTILE 16384
#define K_OFF 65536
#define V_OFF  98304
#define P_OFF 131072
#define ATT_SMEM 147456

#define SCALE0 0.17677669529663687f
#define SCALE1 0.125f
#define SCALE2 0.08838834764831843f

// ---------------- device scratch ----------------
__device__ float g_part[2*2048*3072];
__device__ float g_lsum[2*3*BHS_];
__device__ __half g_xh[MROWS_*D_];
__device__ __half g_xl[MROWS_*D_];
__device__ __half g_Wt[NTOT_*D_];
__device__ __half g_Wot[D_*D_];
__device__ __half g_AO[MROWS_*D_];     // single fp16
__device__ __half g_Qh[B_*H_*S_*DH_];
__device__ __half g_Ql[B_*H_*S_*DH_];
__device__ __half g_K [B_*G_*S_*DH_];
__device__ __half g_Vt[B_*G_*DH_*S_];

// ---------------- matryoshka reorder ----------------
__device__ __forceinline__ int perm16(int h, int d) {
    return (d < 32) ? (h*32 + d)
         : (d < 64) ? (512 + h*32 + (d-32))
                    : (1024 + h*64 + (d-64));
}
__device__ __forceinline__ int perm4(int g, int d) {
    return (d < 32) ? (g*32 + d)
         : (d < 64) ? (128 + g*32 + (d-32))
                    : (256 + g*64 + (d-64));
}

// ---------------- PTX helpers ----------------
__device__ __forceinline__ uint32_t smem_u32(const void* p) {
    uint32_t a;
    asm("{ .reg .u64 t; cvta.to.shared.u64 t, %1; cvt.u32.u64 %0, t; }" : "=r"(a) : "l"(p));
    return a;
}
__device__ __forceinline__ void cp_async16(uint32_t d, const void* g) {
    asm volatile("cp.async.cg.shared.global [%0], [%1], 16;" :: "r"(d), "l"(g));
}
__device__ __forceinline__ void ldsm4(uint32_t* r, uint32_t addr) {
    asm volatile("ldmatrix.sync.aligned.m8n8.x4.shared.b16 {%0,%1,%2,%3}, [%4];"
                 : "=r"(r[0]), "=r"(r[1]), "=r"(r[2]), "=r"(r[3]) : "r"(addr));
}
__device__ __forceinline__ void mma16816(float* c, const uint32_t* a, const uint32_t* b) {
    asm volatile(
        "mma.sync.aligned.m16n8k16.row.col.f32.f16.f16.f32 "
        "{%0,%1,%2,%3}, {%4,%5,%6,%7}, {%8,%9}, {%0,%1,%2,%3};"
        : "+f"(c[0]), "+f"(c[1]), "+f"(c[2]), "+f"(c[3])
        : "r"(a[0]), "r"(a[1]), "r"(a[2]), "r"(a[3]), "r"(b[0]), "r"(b[1]));
}
__device__ __forceinline__ void bar_pair(int id) {
    asm volatile("bar.sync %0, 64;" :: "r"(id) : "memory");
}
__device__ __forceinline__ void f16_split(float v, __half& h, __half& l) {
    h = __float2half(v);
    l = __float2half(v - __half2float(h));
}
__device__ __forceinline__ uint32_t swz64(int r, int c)  { return (uint32_t)r*64  + (uint32_t)((c ^ ((r>>1)&3)) << 4); }
__device__ __forceinline__ uint32_t swz128(int r, int c) { return (uint32_t)r*128 + (uint32_t)((c ^ (r&7)) << 4); }
__device__ __forceinline__ uint32_t swz256(int r, int c) { return (uint32_t)r*256 + (uint32_t)((c ^ (r&7)) << 4); }

// ================= converters =================
__global__ __launch_bounds__(256) void convx_kernel(const float* __restrict__ x) {
    int i = blockIdx.x * 256 + threadIdx.x;
    float4 v = reinterpret_cast<const float4*>(x)[i];
    __half h0,l0,h1,l1,h2,l2,h3,l3;
    f16_split(v.x,h0,l0); f16_split(v.y,h1,l1); f16_split(v.z,h2,l2); f16_split(v.w,h3,l3);
    __half2* ph = reinterpret_cast<__half2*>(g_xh);
    __half2* pl = reinterpret_cast<__half2*>(g_xl);
    ph[2*i]   = __half2(h0,h1); ph[2*i+1] = __half2(h2,h3);
    pl[2*i]   = __half2(l0,l1); pl[2*i+1] = __half2(l2,l3);
}

__global__ __launch_bounds__(256)
void tconv_qkv_kernel(const float* __restrict__ Wq, const float* __restrict__ Wk,
                      const float* __restrict__ Wv) {
    __shared__ float ts[64][65];
    const int tid = threadIdx.x;
    const int n0 = blockIdx.x * 64, k0 = blockIdx.y * 64;
    for (int idx = tid; idx < 4096; idx += 256) {
        int kk = idx >> 6, nn = idx & 63;
        int n = n0 + nn;
        const float* W; int ldw, src;
        if (n < NQ_)            { W = Wq; ldw = NQ_;  src = perm16(n >> 7, n & 127); }
        else if (n < NQ_+NKV_)  { int t = n - NQ_;        W = Wk; ldw = NKV_; src = perm4(t >> 7, t & 127); }
        else                    { int t = n - NQ_ - NKV_; W = Wv; ldw = NKV_; src = perm4(t >> 7, t & 127); }
        ts[kk][nn] = W[(size_t)(k0 + kk) * ldw + src];
    }
    __syncthreads();
    for (int idx = tid; idx < 4096; idx += 256) {
        int nn = idx >> 6, kk = idx & 63;
        g_Wt[(size_t)(n0 + nn) * D_ + k0 + kk] = __float2half(ts[kk][nn]);
    }
}

__global__ __launch_bounds__(256)
void tconv_wo_kernel(const float* __restrict__ Wo) {
    __shared__ float ts[64][65];
    const int tid = threadIdx.x;
    const int n0 = blockIdx.x * 64, k0 = blockIdx.y * 64;
    for (int idx = tid; idx < 4096; idx += 256) {
        int kk = idx >> 6, nn = idx & 63;
        int k = k0 + kk;
        int srcrow = perm16(k >> 7, k & 127);
        ts[kk][nn] = Wo[(size_t)srcrow * D_ + n0 + nn];
    }
    __syncthreads();
    for (int idx = tid; idx < 4096; idx += 256) {
        int nn = idx >> 6, kk = idx & 63;
        g_Wot[(size_t)(n0 + nn) * D_ + k0 + kk] = __float2half(ts[kk][nn]);
    }
}

// ================= QKV GEMM: fp16 2-product (A hi/lo, B single) =================
__global__ __launch_bounds__(256, 2)
void gemm_qkv_kernel(const __half* __restrict__ Ah, const __half* __restrict__ Al,
                     const __half* __restrict__ Bs,
                     const float* __restrict__ bq, const float* __restrict__ bk,
                     const float* __restrict__ bv)
{
    extern __shared__ char smem[];
    const uint32_t sb = smem_u32(smem);
    float* sBias = reinterpret_cast<float*>(smem + 3 * STAGE_GB);

    const int tid  = threadIdx.x;
    const int lane = tid & 31;
    const int wid  = tid >> 5;
    const int wm = wid >> 1;
    const int wn = wid & 1;
    const int n0 = blockIdx.x * 128;
    const int m0 = blockIdx.y * 128;
    const int NK = D_ / KC;

    if (tid < 128) {
        int n = n0 + tid;
        float b;
        if (n < NQ_)            b = bq[perm16(n >> 7, n & 127)];
        else if (n < NQ_+NKV_)  { int t = n - NQ_;        b = bk[perm4(t >> 7, t & 127)]; }
        else                    { int t = n - NQ_ - NKV_; b = bv[perm4(t >> 7, t & 127)]; }
        sBias[tid] = b;
    }

    const __half* srcs[3] = {
        Ah + (size_t)m0 * D_, Al + (size_t)m0 * D_, Bs + (size_t)n0 * D_ };

    auto load_stage = [&](int chunk) {
        const uint32_t st = sb + (uint32_t)(chunk % 3) * STAGE_GB;
        const int k0 = chunk * KC;
        #pragma unroll
        for (int t = 0; t < 3; t++) {
            const __half* s = srcs[t];
            const uint32_t tb = st + t * TILE_GB;
            #pragma unroll
            for (int it = 0; it < 2; it++) {
                int idx = tid + it * 256;
                int r = idx >> 2, c = idx & 3;
                cp_async16(tb + swz64(r, c), s + (size_t)r * D_ + k0 + c * 8);
            }
        }
        asm volatile("cp.async.commit_group;" ::: "memory");
    };

    float acc[2][8][4];
    #pragma unroll
    for (int mi = 0; mi < 2; mi++)
        #pragma unroll
        for (int ni = 0; ni < 8; ni++)
            #pragma unroll
            for (int q = 0; q < 4; q++) acc[mi][ni][q] = 0.f;

    const int mat = lane >> 3, rin = lane & 7;
    const int arow = wm*32 + (mat & 1)*8 + rin;
    const int acb  = (mat >> 1);
    const int brow = wn*64 + (mat >> 1)*8 + rin;
    const int bcb  = (mat & 1);

    load_stage(0);
    load_stage(1);

    for (int i = 0; i < NK; i++) {
        if (i >= NK - 1) asm volatile("cp.async.wait_group 0;" ::: "memory");
        else             asm volatile("cp.async.wait_group 1;" ::: "memory");
        __syncthreads();
        if (i + 2 < NK) load_stage(i + 2);

        const uint32_t st = sb + (uint32_t)(i % 3) * STAGE_GB;
        const uint32_t aH = st, aL = st + TILE_GB, bB = st + 2*TILE_GB;

        #pragma unroll
        for (int kk = 0; kk < 2; kk++) {
            uint32_t ah[2][4], al[2][4];
            #pragma unroll
            for (int mi = 0; mi < 2; mi++) {
                int r = arow + mi*16;
                uint32_t off = swz64(r, kk*2 + acb);
                ldsm4(ah[mi], aH + off);
                ldsm4(al[mi], aL + off);
            }
            uint32_t bf[8][2];
            #pragma unroll
            for (int nb2 = 0; nb2 < 4; nb2++) {
                int r = brow + nb2*16;
                uint32_t off = swz64(r, kk*2 + bcb);
                uint32_t r4[4];
                ldsm4(r4, bB + off);
                bf[2*nb2][0] = r4[0]; bf[2*nb2][1] = r4[1];
                bf[2*nb2+1][0] = r4[2]; bf[2*nb2+1][1] = r4[3];
            }
            #pragma unroll
            for (int mi = 0; mi < 2; mi++)
                #pragma unroll
                for (int ni = 0; ni < 8; ni++)
                    mma16816(acc[mi][ni], ah[mi], bf[ni]);
            #pragma unroll
            for (int mi = 0; mi < 2; mi++)
                #pragma unroll
                for (int ni = 0; ni < 8; ni++)
                    mma16816(acc[mi][ni], al[mi], bf[ni]);
        }
    }

    // ---------- epilogue ----------
    const int g = lane >> 2, tig = lane & 3;
    #pragma unroll
    for (int mi = 0; mi < 2; mi++)
        #pragma unroll
        for (int ni = 0; ni < 8; ni++) {
            int col = wn*64 + ni*8 + tig*2;
            float b0 = sBias[col], b1 = sBias[col + 1];
            #pragma unroll
            for (int half = 0; half < 2; half++) {
                int row = m0 + wm*32 + mi*16 + g + half*8;
                float vx = acc[mi][ni][half*2+0] + b0;
                float vy = acc[mi][ni][half*2+1] + b1;
                int bb = row >> 10, s = row & 1023;
                if (n0 < NQ_) {
                    int h = n0 >> 7;
                    __half hx,lx,hy,ly;
                    f16_split(vx,hx,lx); f16_split(vy,hy,ly);
                    size_t o = ((size_t)((bb*H_ + h)*S_ + s))*DH_ + col;
                    *reinterpret_cast<__half2*>(g_Qh + o) = __half2(hx,hy);
                    *reinterpret_cast<__half2*>(g_Ql + o) = __half2(lx,ly);
                } else if (n0 < NQ_+NKV_) {
                    int gg = (n0 - NQ_) >> 7;
                    size_t o = ((size_t)((bb*G_ + gg)*S_ + s))*DH_ + col;
                    *reinterpret_cast<__half2*>(g_K + o) =
                        __half2(__float2half(vx), __float2half(vy));
                } else {
                    int gg = (n0 - NQ_ - NKV_) >> 7;
                    size_t o = ((size_t)(bb*G_ + gg)*DH_ + col)*S_ + s;
                    g_Vt[o]      = __float2half(vx);
                    g_Vt[o + S_] = __float2half(vy);
                }
            }
        }
}

// ================= out GEMM: fp16 single-product =================
__global__ __launch_bounds__(256, 2)
void gemm_out_kernel(const __half* __restrict__ As, const __half* __restrict__ Bs,
                     float* __restrict__ outp, const float* __restrict__ bo)
{
    extern __shared__ char smem[];
    const uint32_t sb = smem_u32(smem);
    float* sBias = reinterpret_cast<float*>(smem + 3 * STAGE_OB);

    const int tid  = threadIdx.x;
    const int lane = tid & 31;
    const int wid  = tid >> 5;
    const int wm = wid >> 1;
    const int wn = wid & 1;
    const int n0 = blockIdx.x * 128;
    const int m0 = blockIdx.y * 128;
    const int NK = D_ / KC;

    if (tid < 128) sBias[tid] = bo[n0 + tid];

    const __half* srcs[2] = { As + (size_t)m0 * D_, Bs + (size_t)n0 * D_ };

    auto load_stage = [&](int chunk) {
        const uint32_t st = sb + (uint32_t)(chunk % 3) * STAGE_OB;
        const int k0 = chunk * KC;
        #pragma unroll
        for (int t = 0; t < 2; t++) {
            const __half* s = srcs[t];
            const uint32_t tb = st + t * TILE_GB;
            #pragma unroll
            for (int it = 0; it < 2; it++) {
                int idx = tid + it * 256;
                int r = idx >> 2, c = idx & 3;
                cp_async16(tb + swz64(r, c), s + (size_t)r * D_ + k0 + c * 8);
            }
        }
        asm volatile("cp.async.commit_group;" ::: "memory");
    };

    float acc[2][8][4];
    #pragma unroll
    for (int mi = 0; mi < 2; mi++)
        #pragma unroll
        for (int ni = 0; ni < 8; ni++)
            #pragma unroll
            for (int q = 0; q < 4; q++) acc[mi][ni][q] = 0.f;

    const int mat = lane >> 3, rin = lane & 7;
    const int arow = wm*32 + (mat & 1)*8 + rin;
    const int acb  = (mat >> 1);
    const int brow = wn*64 + (mat >> 1)*8 + rin;
    const int bcb  = (mat & 1);

    load_stage(0);
    load_stage(1);

    for (int i = 0; i < NK; i++) {
        if (i >= NK - 1) asm volatile("cp.async.wait_group 0;" ::: "memory");
        else             asm volatile("cp.async.wait_group 1;" ::: "memory");
        __syncthreads();
        if (i + 2 < NK) load_stage(i + 2);

        const uint32_t st = sb + (uint32_t)(i % 3) * STAGE_OB;
        const uint32_t aA = st, bB = st + TILE_GB;

        #pragma unroll
        for (int kk = 0; kk < 2; kk++) {
            uint32_t af[2][4];
            #pragma unroll
            for (int mi = 0; mi < 2; mi++) {
                int r = arow + mi*16;
                ldsm4(af[mi], aA + swz64(r, kk*2 + acb));
            }
            uint32_t bf[8][2];
            #pragma unroll
            for (int nb2 = 0; nb2 < 4; nb2++) {
                int r = brow + nb2*16;
                uint32_t r4[4];
                ldsm4(r4, bB + swz64(r, kk*2 + bcb));
                bf[2*nb2][0] = r4[0]; bf[2*nb2][1] = r4[1];
                bf[2*nb2+1][0] = r4[2]; bf[2*nb2+1][1] = r4[3];
            }
            #pragma unroll
            for (int mi = 0; mi < 2; mi++)
                #pragma unroll
                for (int ni = 0; ni < 8; ni++)
                    mma16816(acc[mi][ni], af[mi], bf[ni]);
        }
    }

    const int g = lane >> 2, tig = lane & 3;
    #pragma unroll
    for (int mi = 0; mi < 2; mi++)
        #pragma unroll
        for (int ni = 0; ni < 8; ni++) {
            int col = wn*64 + ni*8 + tig*2;
            float b0 = sBias[col], b1 = sBias[col + 1];
            #pragma unroll
            for (int half = 0; half < 2; half++) {
                int row = m0 + wm*32 + mi*16 + g + half*8;
                *reinterpret_cast<float2*>(outp + (size_t)row * D_ + n0 + col) =
                    make_float2(acc[mi][ni][half*2+0] + b0, acc[mi][ni][half*2+1] + b1);
            }
        }
}

// ================= fp16 flash attention, split-KV x2, P single =================
__global__ __launch_bounds__(512, 1)
void attn_mma_kernel()
{
    extern __shared__ char smem[];
    const uint32_t sb = smem_u32(smem);
    const int tid = threadIdx.x, lane = tid & 31, wid = tid >> 5;
    const int qt2 = (S_/QT - 1) - blockIdx.x;
    const int h = blockIdx.y;
    const int zz = blockIdx.z & 1, b = blockIdx.z >> 1;
    const int g = h >> 2;
    const int q0 = qt2 * QT;
    const int ktS = zz * (qt2 + 1);
    const int ktE = ktS + qt2 + 1;
    const int wq = (wid >> 1) * 16;
    const int wk = wid & 1;
    const int barid = 1 + (wid >> 1);
    const int mat = lane >> 3, rin = lane & 7;
    const int gq = lane >> 2, tig = lane & 3;

    const __half* Kp  = g_K  + ((size_t)(b*G_ + g) * S_) * DH_;
    const __half* Vp  = g_Vt + (size_t)(b*G_ + g) * DH_ * S_;
    const __half* Qhp = g_Qh + ((size_t)(b*H_ + h) * S_ + q0) * DH_;
    const __half* Qlp = g_Ql + ((size_t)(b*H_ + h) * S_ + q0) * DH_;

    auto issue_KV = [&](int kt) {
        const uint32_t kst = sb + K_OFF + (uint32_t)(kt & 1) * KTILE;
        const uint32_t vst = sb + V_OFF + (uint32_t)(kt & 1) * VTILE;
        const int k0 = kt * KT;
        #pragma unroll
        for (int i = 0; i < 2; i++) {
            int idx = tid + i * 512;
            { int r = idx >> 4, c = idx & 15;
              cp_async16(kst + swz256(r, c), Kp + (size_t)(k0 + r)*DH_ + c*8); }
            { int r = idx >> 3, c = idx & 7;
              cp_async16(vst + swz128(r, c), Vp + (size_t)r*S_ + k0 + c*8); }
        }
        asm volatile("cp.async.commit_group;" ::: "memory");
    };

    #pragma unroll
    for (int i = 0; i < 4; i++) {
        int idx = tid + i * 512; int r = idx >> 4, c = idx & 15;
        cp_async16(sb + swz256(r, c), Qhp + (size_t)r*DH_ + c*8);
        cp_async16(sb + QTILE + swz256(r, c), Qlp + (size_t)r*DH_ + c*8);
    }
    issue_KV(ktS);

    float o0[2][4] = {}, o1[2][4] = {}, o2[4][4] = {};
    float lsum[3][2] = {};

    const int rq = wq + (mat & 1)*8 + rin;
    const uint32_t qrow_off = (uint32_t)rq * 256;
    const int qsw = rq & 7;
    const uint32_t prow_off = (uint32_t)rq * 128;
    char* pwp = smem + P_OFF;
    float* lred = reinterpret_cast<float*>(smem + P_OFF);

    for (int kt = ktS; kt < ktE; kt++) {
        asm volatile("cp.async.wait_group 0;" ::: "memory");
        __syncthreads();
        if (kt + 1 < ktE) issue_KV(kt + 1);

        const int k0 = kt * KT;
        const uint32_t kst = sb + K_OFF + (uint32_t)(kt & 1) * KTILE;
        const uint32_t vst = sb + V_OFF + (uint32_t)(kt & 1) * VTILE;

        float acc[4][4];
        #pragma unroll
        for (int nb = 0; nb < 4; nb++)
            #pragma unroll
            for (int q = 0; q < 4; q++) acc[nb][q] = 0.f;

        auto qk_steps = [&](int kkA, int kkB) {
            #pragma unroll
            for (int kk = kkA; kk < kkB; kk++) {
                uint32_t qh[4], ql[4];
                uint32_t qoff = qrow_off + (uint32_t)(((kk*2 + (mat>>1)) ^ qsw) << 4);
                ldsm4(qh, sb + qoff);
                ldsm4(ql, sb + QTILE + qoff);
                uint32_t bh[4][2];
                #pragma unroll
                for (int nb2 = 0; nb2 < 2; nb2++) {
                    int rk = wk*32 + nb2*16 + (mat >> 1)*8 + rin;
                    uint32_t off = swz256(rk, kk*2 + (mat & 1));
                    uint32_t r4[4];
                    ldsm4(r4, kst + off);
                    bh[2*nb2][0] = r4[0]; bh[2*nb2][1] = r4[1];
                    bh[2*nb2+1][0] = r4[2]; bh[2*nb2+1][1] = r4[3];
                }
                #pragma unroll
                for (int nb = 0; nb < 4; nb++) mma16816(acc[nb], qh, bh[nb]);
                #pragma unroll
                for (int nb = 0; nb < 4; nb++) mma16816(acc[nb], ql, bh[nb]);
            }
        };

        auto do_exp = [&](float scale, float* ls) {
            const int r0g = q0 + wq + gq, r1g = r0g + 8;
            const bool need_mask = (k0 + wk*32 + 31 > q0 + wq);
            #pragma unroll
            for (int nb = 0; nb < 4; nb++) {
                int colg = k0 + wk*32 + nb*8 + tig*2;
                float p0 = __expf(acc[nb][0] * scale);
                float p1 = __expf(acc[nb][1] * scale);
                float p2 = __expf(acc[nb][2] * scale);
                float p3 = __expf(acc[nb][3] * scale);
                if (need_mask) {
                    if (colg     > r0g) p0 = 0.f;
                    if (colg + 1 > r0g) p1 = 0.f;
                    if (colg     > r1g) p2 = 0.f;
                    if (colg + 1 > r1g) p3 = 0.f;
                }
                ls[0] += p0 + p1; ls[1] += p2 + p3;
                int rw0 = wq + gq, rw1 = rw0 + 8;
                int c = wk*4 + nb;
                uint32_t o0b = swz128(rw0, c) + tig*4;
                uint32_t o1b = swz128(rw1, c) + tig*4;
                *reinterpret_cast<__half2*>(pwp + o0b) =
                    __half2(__float2half(p0), __float2half(p1));
                *reinterpret_cast<__half2*>(pwp + o1b) =
                    __half2(__float2half(p2), __float2half(p3));
            }
        };

        auto do_pv = [&](int dbase, float (*oacc)[4], int nb2cnt) {
            #pragma unroll
            for (int kk2 = 0; kk2 < 4; kk2++) {
                uint32_t pah[4];
                uint32_t poff = prow_off + (uint32_t)(((kk2*2 + (mat>>1)) ^ qsw) << 4);
                ldsm4(pah, sb + P_OFF + poff);
                for (int nb2 = 0; nb2 < nb2cnt; nb2++) {
                    int rv = dbase + nb2*16 + (mat >> 1)*8 + rin;
                    uint32_t voff = swz128(rv, kk2*2 + (mat & 1));
                    uint32_t r4[4];
                    ldsm4(r4, vst + voff);
                    uint32_t vh0[2] = {r4[0], r4[1]}, vh1[2] = {r4[2], r4[3]};
                    mma16816(oacc[2*nb2],   pah, vh0);
                    mma16816(oacc[2*nb2+1], pah, vh1);
                }
            }
        };

        qk_steps(0, 2);
        do_exp(SCALE0, lsum[0]);
        bar_pair(barid);
        do_pv(0 + wk*16, o0, 1);
        qk_steps(2, 4);
        bar_pair(barid);
        do_exp(SCALE1, lsum[1]);
        bar_pair(barid);
        do_pv(32 + wk*16, o1, 1);
        qk_steps(4, 8);
        bar_pair(barid);
        do_exp(SCALE2, lsum[2]);
        bar_pair(barid);
        do_pv(64 + wk*32, o2, 2);
    }

    #pragma unroll
    for (int L = 0; L < 3; L++)
        #pragma unroll
        for (int j = 0; j < 2; j++) {
            lsum[L][j] += __shfl_xor_sync(0xffffffffu, lsum[L][j], 1);
            lsum[L][j] += __shfl_xor_sync(0xffffffffu, lsum[L][j], 2);
        }
    __syncthreads();
    if (tig == 0) {
        #pragma unroll
        for (int L = 0; L < 3; L++) {
            lred[L*256 + (wq + gq)*2 + wk]     = lsum[L][0];
            lred[L*256 + (wq + gq + 8)*2 + wk] = lsum[L][1];
        }
    }
    __syncthreads();

    const int r0 = wq + gq, r1 = r0 + 8;

    if (wk == 0 && tig == 0) {
        int idx0 = (b*H_ + h)*S_ + q0 + r0;
        int idx1 = idx0 + 8;
        #pragma unroll
        for (int L = 0; L < 3; L++) {
            g_lsum[(zz*3 + L)*BHS_ + idx0] = lred[L*256 + r0*2] + lred[L*256 + r0*2 + 1];
            g_lsum[(zz*3 + L)*BHS_ + idx1] = lred[L*256 + r1*2] + lred[L*256 + r1*2 + 1];
        }
    }

    float* part = g_part + (size_t)zz * PZ_;
    size_t base0 = ((size_t)(b*S_ + q0 + r0)) * D_ + (size_t)h * DH_;
    size_t base1 = ((size_t)(b*S_ + q0 + r1)) * D_ + (size_t)h * DH_;
    #pragma unroll
    for (int j = 0; j < 2; j++) {
        int d = wk*16 + j*8 + tig*2;
        *reinterpret_cast<float2*>(part + base0 + d)      = make_float2(o0[j][0], o0[j][1]);
        *reinterpret_cast<float2*>(part + base1 + d)      = make_float2(o0[j][2], o0[j][3]);
        *reinterpret_cast<float2*>(part + base0 + 32 + d) = make_float2(o1[j][0], o1[j][1]);
        *reinterpret_cast<float2*>(part + base1 + 32 + d) = make_float2(o1[j][2], o1[j][3]);
    }
    #pragma unroll
    for (int j = 0; j < 4; j++) {
        int d = 64 + wk*32 + j*8 + tig*2;
        *reinterpret_cast<float2*>(part + base0 + d) = make_float2(o2[j][0], o2[j][1]);
        *reinterpret_cast<float2*>(part + base1 + d) = make_float2(o2[j][2], o2[j][3]);
    }
}

// ================= attention combine =================
__global__ __launch_bounds__(256)
void attn_combine()
{
    const int m = blockIdx.x;
    const int col = blockIdx.y * 512 + threadIdx.x * 2;
    float2 p0 = *reinterpret_cast<const float2*>(g_part + (size_t)m*D_ + col);
    float2 p1 = *reinterpret_cast<const float2*>(g_part + PZ_ + (size_t)m*D_ + col);
    const int h = col >> 7, d = col & 127;
    const int L = (d < 32) ? 0 : (d < 64) ? 1 : 2;
    const int b = m >> 10, s = m & 1023;
    const int idx = (b*H_ + h)*S_ + s;
    float ls = g_lsum[L*BHS_ + idx] + g_lsum[(3 + L)*BHS_ + idx];
    float inv = 1.f / ls;
    size_t o = (size_t)m * D_ + col;
    *reinterpret_cast<__half2*>(g_AO + o) =
        __half2(__float2half((p0.x + p1.x) * inv), __float2half((p0.y + p1.y) * inv));
}

// ================= launch =================
extern "C" void kernel_launch(void* const* d_in, const int* in_sizes, int n_in,
                              void* d_out, int out_size)
{
    (void)in_sizes; (void)n_in; (void)out_size;
    const float* x  = (const float*)d_in[0];
    const float* Wq = (const float*)d_in[2];
    const float* bq = (const float*)d_in[3];
    const float* Wk = (const float*)d_in[4];
    const float* bk = (const float*)d_in[5];
    const float* Wv = (const float*)d_in[6];
    const float* bv = (const float*)d_in[7];
    const float* Wo = (const float*)d_in[8];
    const float* bo = (const float*)d_in[9];
    float* out = (float*)d_out;

    convx_kernel<<<MROWS_*D_/4/256, 256>>>(x);
    tconv_qkv_kernel<<<dim3(NTOT_/64, D_/64), 256>>>(Wq, Wk, Wv);
    tconv_wo_kernel<<<dim3(D_/64, D_/64), 256>>>(Wo);

    static __half *pxh = nullptr, *pxl, *pwt, *pwot, *pao;
    if (!pxh) {
        cudaGetSymbolAddress((void**)&pxh, g_xh);
        cudaGetSymbolAddress((void**)&pxl, g_xl);
        cudaGetSymbolAddress((void**)&pwt, g_Wt);
        cudaGetSymbolAddress((void**)&pwot, g_Wot);
        cudaGetSymbolAddress((void**)&pao, g_AO);
    }

    static bool attr_set = false;
    if (!attr_set) {
        cudaFuncSetAttribute(gemm_qkv_kernel, cudaFuncAttributeMaxDynamicSharedMemorySize, GEMM_SMEM);
        cudaFuncSetAttribute(gemm_out_kernel, cudaFuncAttributeMaxDynamicSharedMemorySize, GEMM_O_SMEM);
        cudaFuncSetAttribute(attn_mma_kernel, cudaFuncAttributeMaxDynamicSharedMemorySize, ATT_SMEM);
        attr_set = true;
    }

    gemm_qkv_kernel<<<dim3(NTOT_/128, MROWS_/128), 256, GEMM_SMEM>>>(
        pxh, pxl, pwt, bq, bk, bv);

    attn_mma_kernel<<<dim3(S_/QT, H_, B_*2), 512, ATT_SMEM>>>();
    attn_combine<<<dim3(MROWS_, 4), 256>>>();

    gemm_out_kernel<<<dim3(D_/128, MROWS_/128), 256, GEMM_O_SMEM>>>(
        pao, pwot, out, bo);
}

// round 15
// speedup vs baseline: 1.9985x; 1.2602x over previous
#include <cuda_runtime.h>
#include <cuda_fp16.h>
#include <stdint.h>
#include <cstdint>
#include <math.h>

#define B_ 2
#define S_ 1024
#define D_ 2048
#define H_ 16
#define G_ 4
#define DH_ 128
#define NQ_ 2048
#define NKV_ 512
#define NTOT_ 3072
#define MROWS_ 2048
#define PZ_ (2048*3072)
#define BHS_ (B_*H_*S_)

// GEMMs: A single + B single, KC=32, pitch 64 swizzled, 3 stages
#define KC 32
#define TILE_GB 8192
#define STAGE_GB (2 * TILE_GB)
#define GEMM_SMEM (3 * STAGE_GB + 512)

// Attention (all single fp16)
#define QT 128
#define KT 64
#define QTILE 32768
#define KTILE 16384
#define VTILE 16384
#define PTILE 16384
#define K_OFF 32768
#define V_OFF 65536
#define P_OFF 98304
#define ATT_SMEM 114688

#define SCALE0 0.17677669529663687f
#define SCALE1 0.125f
#define SCALE2 0.08838834764831843f

// ---------------- device scratch ----------------
__device__ float g_part[2*2048*3072];
__device__ float g_lsum[2*3*BHS_];
__device__ __half g_x [MROWS_*D_];
__device__ __half g_Wt[NTOT_*D_];
__device__ __half g_Wot[D_*D_];
__device__ __half g_AO[MROWS_*D_];
__device__ __half g_Q [B_*H_*S_*DH_];
__device__ __half g_K [B_*G_*S_*DH_];
__device__ __half g_Vt[B_*G_*DH_*S_];

// ---------------- matryoshka reorder ----------------
__device__ __forceinline__ int perm16(int h, int d) {
    return (d < 32) ? (h*32 + d)
         : (d < 64) ? (512 + h*32 + (d-32))
                    : (1024 + h*64 + (d-64));
}
__device__ __forceinline__ int perm4(int g, int d) {
    return (d < 32) ? (g*32 + d)
         : (d < 64) ? (128 + g*32 + (d-32))
                    : (256 + g*64 + (d-64));
}

// ---------------- PTX helpers ----------------
__device__ __forceinline__ uint32_t smem_u32(const void* p) {
    uint32_t a;
    asm("{ .reg .u64 t; cvta.to.shared.u64 t, %1; cvt.u32.u64 %0, t; }" : "=r"(a) : "l"(p));
    return a;
}
__device__ __forceinline__ void cp_async16(uint32_t d, const void* g) {
    asm volatile("cp.async.cg.shared.global [%0], [%1], 16;" :: "r"(d), "l"(g));
}
__device__ __forceinline__ void ldsm4(uint32_t* r, uint32_t addr) {
    asm volatile("ldmatrix.sync.aligned.m8n8.x4.shared.b16 {%0,%1,%2,%3}, [%4];"
                 : "=r"(r[0]), "=r"(r[1]), "=r"(r[2]), "=r"(r[3]) : "r"(addr));
}
__device__ __forceinline__ void mma16816(float* c, const uint32_t* a, const uint32_t* b) {
    asm volatile(
        "mma.sync.aligned.m16n8k16.row.col.f32.f16.f16.f32 "
        "{%0,%1,%2,%3}, {%4,%5,%6,%7}, {%8,%9}, {%0,%1,%2,%3};"
        : "+f"(c[0]), "+f"(c[1]), "+f"(c[2]), "+f"(c[3])
        : "r"(a[0]), "r"(a[1]), "r"(a[2]), "r"(a[3]), "r"(b[0]), "r"(b[1]));
}
__device__ __forceinline__ void bar_pair(int id) {
    asm volatile("bar.sync %0, 64;" :: "r"(id) : "memory");
}
__device__ __forceinline__ uint32_t swz64(int r, int c)  { return (uint32_t)r*64  + (uint32_t)((c ^ ((r>>1)&3)) << 4); }
__device__ __forceinline__ uint32_t swz128(int r, int c) { return (uint32_t)r*128 + (uint32_t)((c ^ (r&7)) << 4); }
__device__ __forceinline__ uint32_t swz256(int r, int c) { return (uint32_t)r*256 + (uint32_t)((c ^ (r&7)) << 4); }

// ================= converters =================
__global__ __launch_bounds__(256) void convx_kernel(const float* __restrict__ x) {
    int i = blockIdx.x * 256 + threadIdx.x;
    float4 v = reinterpret_cast<const float4*>(x)[i];
    __half2* p = reinterpret_cast<__half2*>(g_x);
    p[2*i]   = __half2(__float2half(v.x), __float2half(v.y));
    p[2*i+1] = __half2(__float2half(v.z), __float2half(v.w));
}

__global__ __launch_bounds__(256)
void tconv_qkv_kernel(const float* __restrict__ Wq, const float* __restrict__ Wk,
                      const float* __restrict__ Wv) {
    __shared__ float ts[64][65];
    const int tid = threadIdx.x;
    const int n0 = blockIdx.x * 64, k0 = blockIdx.y * 64;
    for (int idx = tid; idx < 4096; idx += 256) {
        int kk = idx >> 6, nn = idx & 63;
        int n = n0 + nn;
        const float* W; int ldw, src;
        if (n < NQ_)            { W = Wq; ldw = NQ_;  src = perm16(n >> 7, n & 127); }
        else if (n < NQ_+NKV_)  { int t = n - NQ_;        W = Wk; ldw = NKV_; src = perm4(t >> 7, t & 127); }
        else                    { int t = n - NQ_ - NKV_; W = Wv; ldw = NKV_; src = perm4(t >> 7, t & 127); }
        ts[kk][nn] = W[(size_t)(k0 + kk) * ldw + src];
    }
    __syncthreads();
    for (int idx = tid; idx < 4096; idx += 256) {
        int nn = idx >> 6, kk = idx & 63;
        g_Wt[(size_t)(n0 + nn) * D_ + k0 + kk] = __float2half(ts[kk][nn]);
    }
}

__global__ __launch_bounds__(256)
void tconv_wo_kernel(const float* __restrict__ Wo) {
    __shared__ float ts[64][65];
    const int tid = threadIdx.x;
    const int n0 = blockIdx.x * 64, k0 = blockIdx.y * 64;
    for (int idx = tid; idx < 4096; idx += 256) {
        int kk = idx >> 6, nn = idx & 63;
        int k = k0 + kk;
        int srcrow = perm16(k >> 7, k & 127);
        ts[kk][nn] = Wo[(size_t)srcrow * D_ + n0 + nn];
    }
    __syncthreads();
    for (int idx = tid; idx < 4096; idx += 256) {
        int nn = idx >> 6, kk = idx & 63;
        g_Wot[(size_t)(n0 + nn) * D_ + k0 + kk] = __float2half(ts[kk][nn]);
    }
}

// ================= fp16 single-product GEMM =================
// MODE 0: QKV (scatter to g_Q/g_K/g_Vt with bias), MODE 1: out (fp32, bq carries bo)
template<int MODE>
__global__ __launch_bounds__(256, 2)
void gemm_mma_kernel(const __half* __restrict__ As, const __half* __restrict__ Bs,
                     float* __restrict__ outp,
                     const float* __restrict__ bq, const float* __restrict__ bk,
                     const float* __restrict__ bv)
{
    extern __shared__ char smem[];
    const uint32_t sb = smem_u32(smem);
    float* sBias = reinterpret_cast<float*>(smem + 3 * STAGE_GB);

    const int tid  = threadIdx.x;
    const int lane = tid & 31;
    const int wid  = tid >> 5;
    const int wm = wid >> 1;
    const int wn = wid & 1;
    const int n0 = blockIdx.x * 128;
    const int m0 = blockIdx.y * 128;
    const int NK = D_ / KC;

    if (tid < 128) {
        int n = n0 + tid;
        float b;
        if (MODE == 0) {
            if (n < NQ_)            b = bq[perm16(n >> 7, n & 127)];
            else if (n < NQ_+NKV_)  { int t = n - NQ_;        b = bk[perm4(t >> 7, t & 127)]; }
            else                    { int t = n - NQ_ - NKV_; b = bv[perm4(t >> 7, t & 127)]; }
        } else b = bq[n];
        sBias[tid] = b;
    }

    const __half* srcs[2] = { As + (size_t)m0 * D_, Bs + (size_t)n0 * D_ };

    auto load_stage = [&](int chunk) {
        const uint32_t st = sb + (uint32_t)(chunk % 3) * STAGE_GB;
        const int k0 = chunk * KC;
        #pragma unroll
        for (int t = 0; t < 2; t++) {
            const __half* s = srcs[t];
            const uint32_t tb = st + t * TILE_GB;
            #pragma unroll
            for (int it = 0; it < 2; it++) {
                int idx = tid + it * 256;
                int r = idx >> 2, c = idx & 3;
                cp_async16(tb + swz64(r, c), s + (size_t)r * D_ + k0 + c * 8);
            }
        }
        asm volatile("cp.async.commit_group;" ::: "memory");
    };

    float acc[2][8][4];
    #pragma unroll
    for (int mi = 0; mi < 2; mi++)
        #pragma unroll
        for (int ni = 0; ni < 8; ni++)
            #pragma unroll
            for (int q = 0; q < 4; q++) acc[mi][ni][q] = 0.f;

    const int mat = lane >> 3, rin = lane & 7;
    const int arow = wm*32 + (mat & 1)*8 + rin;
    const int acb  = (mat >> 1);
    const int brow = wn*64 + (mat >> 1)*8 + rin;
    const int bcb  = (mat & 1);

    load_stage(0);
    load_stage(1);

    for (int i = 0; i < NK; i++) {
        if (i >= NK - 1) asm volatile("cp.async.wait_group 0;" ::: "memory");
        else             asm volatile("cp.async.wait_group 1;" ::: "memory");
        __syncthreads();
        if (i + 2 < NK) load_stage(i + 2);

        const uint32_t st = sb + (uint32_t)(i % 3) * STAGE_GB;
        const uint32_t aA = st, bB = st + TILE_GB;

        #pragma unroll
        for (int kk = 0; kk < 2; kk++) {
            uint32_t af[2][4];
            #pragma unroll
            for (int mi = 0; mi < 2; mi++) {
                int r = arow + mi*16;
                ldsm4(af[mi], aA + swz64(r, kk*2 + acb));
            }
            uint32_t bf[8][2];
            #pragma unroll
            for (int nb2 = 0; nb2 < 4; nb2++) {
                int r = brow + nb2*16;
                uint32_t r4[4];
                ldsm4(r4, bB + swz64(r, kk*2 + bcb));
                bf[2*nb2][0] = r4[0]; bf[2*nb2][1] = r4[1];
                bf[2*nb2+1][0] = r4[2]; bf[2*nb2+1][1] = r4[3];
            }
            #pragma unroll
            for (int mi = 0; mi < 2; mi++)
                #pragma unroll
                for (int ni = 0; ni < 8; ni++)
                    mma16816(acc[mi][ni], af[mi], bf[ni]);
        }
    }

    // ---------- epilogue ----------
    const int g = lane >> 2, tig = lane & 3;
    #pragma unroll
    for (int mi = 0; mi < 2; mi++)
        #pragma unroll
        for (int ni = 0; ni < 8; ni++) {
            int col = wn*64 + ni*8 + tig*2;
            float b0 = sBias[col], b1 = sBias[col + 1];
            #pragma unroll
            for (int half = 0; half < 2; half++) {
                int row = m0 + wm*32 + mi*16 + g + half*8;
                float vx = acc[mi][ni][half*2+0] + b0;
                float vy = acc[mi][ni][half*2+1] + b1;
                if (MODE == 0) {
                    int bb = row >> 10, s = row & 1023;
                    __half2 hv = __half2(__float2half(vx), __float2half(vy));
                    if (n0 < NQ_) {
                        int h = n0 >> 7;
                        size_t o = ((size_t)((bb*H_ + h)*S_ + s))*DH_ + col;
                        *reinterpret_cast<__half2*>(g_Q + o) = hv;
                    } else if (n0 < NQ_+NKV_) {
                        int gg = (n0 - NQ_) >> 7;
                        size_t o = ((size_t)((bb*G_ + gg)*S_ + s))*DH_ + col;
                        *reinterpret_cast<__half2*>(g_K + o) = hv;
                    } else {
                        int gg = (n0 - NQ_ - NKV_) >> 7;
                        size_t o = ((size_t)(bb*G_ + gg)*DH_ + col)*S_ + s;
                        g_Vt[o]      = __float2half(vx);
                        g_Vt[o + S_] = __float2half(vy);
                    }
                } else {
                    *reinterpret_cast<float2*>(outp + (size_t)row * D_ + n0 + col) =
                        make_float2(vx, vy);
                }
            }
        }
}

// ================= fp16 flash attention, split-KV x2, all single =================
__global__ __launch_bounds__(512, 1)
void attn_mma_kernel()
{
    extern __shared__ char smem[];
    const uint32_t sb = smem_u32(smem);
    const int tid = threadIdx.x, lane = tid & 31, wid = tid >> 5;
    const int qt2 = (S_/QT - 1) - blockIdx.x;
    const int h = blockIdx.y;
    const int zz = blockIdx.z & 1, b = blockIdx.z >> 1;
    const int g = h >> 2;
    const int q0 = qt2 * QT;
    const int ktS = zz * (qt2 + 1);
    const int ktE = ktS + qt2 + 1;
    const int wq = (wid >> 1) * 16;
    const int wk = wid & 1;
    const int barid = 1 + (wid >> 1);
    const int mat = lane >> 3, rin = lane & 7;
    const int gq = lane >> 2, tig = lane & 3;

    const __half* Kp = g_K  + ((size_t)(b*G_ + g) * S_) * DH_;
    const __half* Vp = g_Vt + (size_t)(b*G_ + g) * DH_ * S_;
    const __half* Qp = g_Q  + ((size_t)(b*H_ + h) * S_ + q0) * DH_;

    auto issue_KV = [&](int kt) {
        const uint32_t kst = sb + K_OFF + (uint32_t)(kt & 1) * KTILE;
        const uint32_t vst = sb + V_OFF + (uint32_t)(kt & 1) * VTILE;
        const int k0 = kt * KT;
        #pragma unroll
        for (int i = 0; i < 2; i++) {
            int idx = tid + i * 512;
            { int r = idx >> 4, c = idx & 15;
              cp_async16(kst + swz256(r, c), Kp + (size_t)(k0 + r)*DH_ + c*8); }
            { int r = idx >> 3, c = idx & 7;
              cp_async16(vst + swz128(r, c), Vp + (size_t)r*S_ + k0 + c*8); }
        }
        asm volatile("cp.async.commit_group;" ::: "memory");
    };

    #pragma unroll
    for (int i = 0; i < 4; i++) {
        int idx = tid + i * 512; int r = idx >> 4, c = idx & 15;
        cp_async16(sb + swz256(r, c), Qp + (size_t)r*DH_ + c*8);
    }
    issue_KV(ktS);

    float o0[2][4] = {}, o1[2][4] = {}, o2[4][4] = {};
    float lsum[3][2] = {};

    const int rq = wq + (mat & 1)*8 + rin;
    const uint32_t qrow_off = (uint32_t)rq * 256;
    const int qsw = rq & 7;
    const uint32_t prow_off = (uint32_t)rq * 128;
    char* pwp = smem + P_OFF;
    float* lred = reinterpret_cast<float*>(smem + P_OFF);

    for (int kt = ktS; kt < ktE; kt++) {
        asm volatile("cp.async.wait_group 0;" ::: "memory");
        __syncthreads();
        if (kt + 1 < ktE) issue_KV(kt + 1);

        const int k0 = kt * KT;
        const uint32_t kst = sb + K_OFF + (uint32_t)(kt & 1) * KTILE;
        const uint32_t vst = sb + V_OFF + (uint32_t)(kt & 1) * VTILE;

        float acc[4][4];
        #pragma unroll
        for (int nb = 0; nb < 4; nb++)
            #pragma unroll
            for (int q = 0; q < 4; q++) acc[nb][q] = 0.f;

        auto qk_steps = [&](int kkA, int kkB) {
            #pragma unroll
            for (int kk = kkA; kk < kkB; kk++) {
                uint32_t qh[4];
                uint32_t qoff = qrow_off + (uint32_t)(((kk*2 + (mat>>1)) ^ qsw) << 4);
                ldsm4(qh, sb + qoff);
                uint32_t bh[4][2];
                #pragma unroll
                for (int nb2 = 0; nb2 < 2; nb2++) {
                    int rk = wk*32 + nb2*16 + (mat >> 1)*8 + rin;
                    uint32_t off = swz256(rk, kk*2 + (mat & 1));
                    uint32_t r4[4];
                    ldsm4(r4, kst + off);
                    bh[2*nb2][0] = r4[0]; bh[2*nb2][1] = r4[1];
                    bh[2*nb2+1][0] = r4[2]; bh[2*nb2+1][1] = r4[3];
                }
                #pragma unroll
                for (int nb = 0; nb < 4; nb++) mma16816(acc[nb], qh, bh[nb]);
            }
        };

        auto do_exp = [&](float scale, float* ls) {
            const int r0g = q0 + wq + gq, r1g = r0g + 8;
            const bool need_mask = (k0 + wk*32 + 31 > q0 + wq);
            #pragma unroll
            for (int nb = 0; nb < 4; nb++) {
                int colg = k0 + wk*32 + nb*8 + tig*2;
                float p0 = __expf(acc[nb][0] * scale);
                float p1 = __expf(acc[nb][1] * scale);
                float p2 = __expf(acc[nb][2] * scale);
                float p3 = __expf(acc[nb][3] * scale);
                if (need_mask) {
                    if (colg     > r0g) p0 = 0.f;
                    if (colg + 1 > r0g) p1 = 0.f;
                    if (colg     > r1g) p2 = 0.f;
                    if (colg + 1 > r1g) p3 = 0.f;
                }
                ls[0] += p0 + p1; ls[1] += p2 + p3;
                int rw0 = wq + gq, rw1 = rw0 + 8;
                int c = wk*4 + nb;
                uint32_t o0b = swz128(rw0, c) + tig*4;
                uint32_t o1b = swz128(rw1, c) + tig*4;
                *reinterpret_cast<__half2*>(pwp + o0b) =
                    __half2(__float2half(p0), __float2half(p1));
                *reinterpret_cast<__half2*>(pwp + o1b) =
                    __half2(__float2half(p2), __float2half(p3));
            }
        };

        auto do_pv = [&](int dbase, float (*oacc)[4], int nb2cnt) {
            #pragma unroll
            for (int kk2 = 0; kk2 < 4; kk2++) {
                uint32_t pah[4];
                uint32_t poff = prow_off + (uint32_t)(((kk2*2 + (mat>>1)) ^ qsw) << 4);
                ldsm4(pah, sb + P_OFF + poff);
                for (int nb2 = 0; nb2 < nb2cnt; nb2++) {
                    int rv = dbase + nb2*16 + (mat >> 1)*8 + rin;
                    uint32_t voff = swz128(rv, kk2*2 + (mat & 1));
                    uint32_t r4[4];
                    ldsm4(r4, vst + voff);
                    uint32_t vh0[2] = {r4[0], r4[1]}, vh1[2] = {r4[2], r4[3]};
                    mma16816(oacc[2*nb2],   pah, vh0);
                    mma16816(oacc[2*nb2+1], pah, vh1);
                }
            }
        };

        qk_steps(0, 2);
        do_exp(SCALE0, lsum[0]);
        bar_pair(barid);
        do_pv(0 + wk*16, o0, 1);
        qk_steps(2, 4);
        bar_pair(barid);
        do_exp(SCALE1, lsum[1]);
        bar_pair(barid);
        do_pv(32 + wk*16, o1, 1);
        qk_steps(4, 8);
        bar_pair(barid);
        do_exp(SCALE2, lsum[2]);
        bar_pair(barid);
        do_pv(64 + wk*32, o2, 2);
    }

    #pragma unroll
    for (int L = 0; L < 3; L++)
        #pragma unroll
        for (int j = 0; j < 2; j++) {
            lsum[L][j] += __shfl_xor_sync(0xffffffffu, lsum[L][j], 1);
            lsum[L][j] += __shfl_xor_sync(0xffffffffu, lsum[L][j], 2);
        }
    __syncthreads();
    if (tig == 0) {
        #pragma unroll
        for (int L = 0; L < 3; L++) {
            lred[L*256 + (wq + gq)*2 + wk]     = lsum[L][0];
            lred[L*256 + (wq + gq + 8)*2 + wk] = lsum[L][1];
        }
    }
    __syncthreads();

    const int r0 = wq + gq, r1 = r0 + 8;

    if (wk == 0 && tig == 0) {
        int idx0 = (b*H_ + h)*S_ + q0 + r0;
        int idx1 = idx0 + 8;
        #pragma unroll
        for (int L = 0; L < 3; L++) {
            g_lsum[(zz*3 + L)*BHS_ + idx0] = lred[L*256 + r0*2] + lred[L*256 + r0*2 + 1];
            g_lsum[(zz*3 + L)*BHS_ + idx1] = lred[L*256 + r1*2] + lred[L*256 + r1*2 + 1];
        }
    }

    float* part = g_part + (size_t)zz * PZ_;
    size_t base0 = ((size_t)(b*S_ + q0 + r0)) * D_ + (size_t)h * DH_;
    size_t base1 = ((size_t)(b*S_ + q0 + r1)) * D_ + (size_t)h * DH_;
    #pragma unroll
    for (int j = 0; j < 2; j++) {
        int d = wk*16 + j*8 + tig*2;
        *reinterpret_cast<float2*>(part + base0 + d)      = make_float2(o0[j][0], o0[j][1]);
        *reinterpret_cast<float2*>(part + base1 + d)      = make_float2(o0[j][2], o0[j][3]);
        *reinterpret_cast<float2*>(part + base0 + 32 + d) = make_float2(o1[j][0], o1[j][1]);
        *reinterpret_cast<float2*>(part + base1 + 32 + d) = make_float2(o1[j][2], o1[j][3]);
    }
    #pragma unroll
    for (int j = 0; j < 4; j++) {
        int d = 64 + wk*32 + j*8 + tig*2;
        *reinterpret_cast<float2*>(part + base0 + d) = make_float2(o2[j][0], o2[j][1]);
        *reinterpret_cast<float2*>(part + base1 + d) = make_float2(o2[j][2], o2[j][3]);
    }
}

// ================= attention combine =================
__global__ __launch_bounds__(256)
void attn_combine()
{
    const int m = blockIdx.x;
    const int col = blockIdx.y * 512 + threadIdx.x * 2;
    float2 p0 = *reinterpret_cast<const float2*>(g_part + (size_t)m*D_ + col);
    float2 p1 = *reinterpret_cast<const float2*>(g_part + PZ_ + (size_t)m*D_ + col);
    const int h = col >> 7, d = col & 127;
    const int L = (d < 32) ? 0 : (d < 64) ? 1 : 2;
    const int b = m >> 10, s = m & 1023;
    const int idx = (b*H_ + h)*S_ + s;
    float ls = g_lsum[L*BHS_ + idx] + g_lsum[(3 + L)*BHS_ + idx];
    float inv = 1.f / ls;
    size_t o = (size_t)m * D_ + col;
    *reinterpret_cast<__half2*>(g_AO + o) =
        __half2(__float2half((p0.x + p1.x) * inv), __float2half((p0.y + p1.y) * inv));
}

// ================= launch =================
extern "C" void kernel_launch(void* const* d_in, const int* in_sizes, int n_in,
                              void* d_out, int out_size)
{
    (void)in_sizes; (void)n_in; (void)out_size;
    const float* x  = (const float*)d_in[0];
    const float* Wq = (const float*)d_in[2];
    const float* bq = (const float*)d_in[3];
    const float* Wk = (const float*)d_in[4];
    const float* bk = (const float*)d_in[5];
    const float* Wv = (const float*)d_in[6];
    const float* bv = (const float*)d_in[7];
    const float* Wo = (const float*)d_in[8];
    const float* bo = (const float*)d_in[9];
    float* out = (float*)d_out;

    convx_kernel<<<MROWS_*D_/4/256, 256>>>(x);
    tconv_qkv_kernel<<<dim3(NTOT_/64, D_/64), 256>>>(Wq, Wk, Wv);
    tconv_wo_kernel<<<dim3(D_/64, D_/64), 256>>>(Wo);

    static __half *px = nullptr, *pwt, *pwot, *pao;
    if (!px) {
        cudaGetSymbolAddress((void**)&px, g_x);
        cudaGetSymbolAddress((void**)&pwt, g_Wt);
        cudaGetSymbolAddress((void**)&pwot, g_Wot);
        cudaGetSymbolAddress((void**)&pao, g_AO);
    }

    static bool attr_set = false;
    if (!attr_set) {
        cudaFuncSetAttribute(gemm_mma_kernel<0>, cudaFuncAttributeMaxDynamicSharedMemorySize, GEMM_SMEM);
        cudaFuncSetAttribute(gemm_mma_kernel<1>, cudaFuncAttributeMaxDynamicSharedMemorySize, GEMM_SMEM);
        cudaFuncSetAttribute(attn_mma_kernel, cudaFuncAttributeMaxDynamicSharedMemorySize, ATT_SMEM);
        attr_set = true;
    }

    gemm_mma_kernel<0><<<dim3(NTOT_/128, MROWS_/128), 256, GEMM_SMEM>>>(
        px, pwt, nullptr, bq, bk, bv);

    attn_mma_kernel<<<dim3(S_/QT, H_, B_*2), 512, ATT_SMEM>>>();
    attn_combine<<<dim3(MROWS_, 4), 256>>>();

    gemm_mma_kernel<1><<<dim3(D_/128, MROWS_/128), 256, GEMM_SMEM>>>(
        pao, pwot, out, bo, nullptr, nullptr);
}

// round 16
// speedup vs baseline: 2.2042x; 1.1029x over previous
#include <cuda_runtime.h>
#include <cuda_fp16.h>
#include <stdint.h>
#include <cstdint>
#include <math.h>

#define B_ 2
#define S_ 1024
#define D_ 2048
#define H_ 16
#define G_ 4
#define DH_ 128
#define NQ_ 2048
#define NKV_ 512
#define NTOT_ 3072
#define MROWS_ 2048
#define PZ_ (2048*3072)
#define BHS_ (B_*H_*S_)

// GEMMs: single fp16, KC=64, pitch 128 swizzled, 3 stages
#define KC 64
#define TILE_GB 16384
#define STAGE_GB (2 * TILE_GB)
#define GEMM_SMEM (3 * STAGE_GB + 512)

// Attention (all single fp16, 3 P regions)
#define QT 128
#define KT 64
#define QTILE 32768
#define KTILE 16384
#define VTILE 16384
#define PTILE 16384
#define K_OFF 32768
#define V_OFF 65536
#define P_OFF 98304
#define ATT_SMEM 147456

#define SCALE0 0.17677669529663687f
#define SCALE1 0.125f
#define SCALE2 0.08838834764831843f

// ---------------- device scratch ----------------
__device__ float g_part[2*2048*3072];
__device__ float g_lsum[2*3*BHS_];
__device__ __half g_x [MROWS_*D_];
__device__ __half g_Wt[NTOT_*D_];
__device__ __half g_Wot[D_*D_];
__device__ __half g_AO[MROWS_*D_];
__device__ __half g_Q [B_*H_*S_*DH_];
__device__ __half g_K [B_*G_*S_*DH_];
__device__ __half g_Vt[B_*G_*DH_*S_];

// ---------------- matryoshka reorder ----------------
__device__ __forceinline__ int perm16(int h, int d) {
    return (d < 32) ? (h*32 + d)
         : (d < 64) ? (512 + h*32 + (d-32))
                    : (1024 + h*64 + (d-64));
}
__device__ __forceinline__ int perm4(int g, int d) {
    return (d < 32) ? (g*32 + d)
         : (d < 64) ? (128 + g*32 + (d-32))
                    : (256 + g*64 + (d-64));
}

// ---------------- PTX helpers ----------------
__device__ __forceinline__ uint32_t smem_u32(const void* p) {
    uint32_t a;
    asm("{ .reg .u64 t; cvta.to.shared.u64 t, %1; cvt.u32.u64 %0, t; }" : "=r"(a) : "l"(p));
    return a;
}
__device__ __forceinline__ void cp_async16(uint32_t d, const void* g) {
    asm volatile("cp.async.cg.shared.global [%0], [%1], 16;" :: "r"(d), "l"(g));
}
__device__ __forceinline__ void ldsm4(uint32_t* r, uint32_t addr) {
    asm volatile("ldmatrix.sync.aligned.m8n8.x4.shared.b16 {%0,%1,%2,%3}, [%4];"
                 : "=r"(r[0]), "=r"(r[1]), "=r"(r[2]), "=r"(r[3]) : "r"(addr));
}
__device__ __forceinline__ void mma16816(float* c, const uint32_t* a, const uint32_t* b) {
    asm volatile(
        "mma.sync.aligned.m16n8k16.row.col.f32.f16.f16.f32 "
        "{%0,%1,%2,%3}, {%4,%5,%6,%7}, {%8,%9}, {%0,%1,%2,%3};"
        : "+f"(c[0]), "+f"(c[1]), "+f"(c[2]), "+f"(c[3])
        : "r"(a[0]), "r"(a[1]), "r"(a[2]), "r"(a[3]), "r"(b[0]), "r"(b[1]));
}
__device__ __forceinline__ void bar_pair(int id) {
    asm volatile("bar.sync %0, 64;" :: "r"(id) : "memory");
}
__device__ __forceinline__ uint32_t swz128(int r, int c) { return (uint32_t)r*128 + (uint32_t)((c ^ (r&7)) << 4); }
__device__ __forceinline__ uint32_t swz256(int r, int c) { return (uint32_t)r*256 + (uint32_t)((c ^ (r&7)) << 4); }

// ================= converters =================
__global__ __launch_bounds__(256) void convx_kernel(const float* __restrict__ x) {
    int i = blockIdx.x * 256 + threadIdx.x;
    float4 v = reinterpret_cast<const float4*>(x)[i];
    __half2* p = reinterpret_cast<__half2*>(g_x);
    p[2*i]   = __half2(__float2half(v.x), __float2half(v.y));
    p[2*i+1] = __half2(__float2half(v.z), __float2half(v.w));
}

__global__ __launch_bounds__(256)
void tconv_qkv_kernel(const float* __restrict__ Wq, const float* __restrict__ Wk,
                      const float* __restrict__ Wv) {
    __shared__ float ts[64][65];
    const int tid = threadIdx.x;
    const int n0 = blockIdx.x * 64, k0 = blockIdx.y * 64;
    for (int idx = tid; idx < 4096; idx += 256) {
        int kk = idx >> 6, nn = idx & 63;
        int n = n0 + nn;
        const float* W; int ldw, src;
        if (n < NQ_)            { W = Wq; ldw = NQ_;  src = perm16(n >> 7, n & 127); }
        else if (n < NQ_+NKV_)  { int t = n - NQ_;        W = Wk; ldw = NKV_; src = perm4(t >> 7, t & 127); }
        else                    { int t = n - NQ_ - NKV_; W = Wv; ldw = NKV_; src = perm4(t >> 7, t & 127); }
        ts[kk][nn] = W[(size_t)(k0 + kk) * ldw + src];
    }
    __syncthreads();
    for (int idx = tid; idx < 4096; idx += 256) {
        int nn = idx >> 6, kk = idx & 63;
        g_Wt[(size_t)(n0 + nn) * D_ + k0 + kk] = __float2half(ts[kk][nn]);
    }
}

__global__ __launch_bounds__(256)
void tconv_wo_kernel(const float* __restrict__ Wo) {
    __shared__ float ts[64][65];
    const int tid = threadIdx.x;
    const int n0 = blockIdx.x * 64, k0 = blockIdx.y * 64;
    for (int idx = tid; idx < 4096; idx += 256) {
        int kk = idx >> 6, nn = idx & 63;
        int k = k0 + kk;
        int srcrow = perm16(k >> 7, k & 127);
        ts[kk][nn] = Wo[(size_t)srcrow * D_ + n0 + nn];
    }
    __syncthreads();
    for (int idx = tid; idx < 4096; idx += 256) {
        int nn = idx >> 6, kk = idx & 63;
        g_Wot[(size_t)(n0 + nn) * D_ + k0 + kk] = __float2half(ts[kk][nn]);
    }
}

// ================= fp16 single-product GEMM, KC=64 =================
template<int MODE>
__global__ __launch_bounds__(256, 2)
void gemm_mma_kernel(const __half* __restrict__ As, const __half* __restrict__ Bs,
                     float* __restrict__ outp,
                     const float* __restrict__ bq, const float* __restrict__ bk,
                     const float* __restrict__ bv)
{
    extern __shared__ char smem[];
    const uint32_t sb = smem_u32(smem);
    float* sBias = reinterpret_cast<float*>(smem + 3 * STAGE_GB);

    const int tid  = threadIdx.x;
    const int lane = tid & 31;
    const int wid  = tid >> 5;
    const int wm = wid >> 1;
    const int wn = wid & 1;
    const int n0 = blockIdx.x * 128;
    const int m0 = blockIdx.y * 128;
    const int NK = D_ / KC;   // 32

    if (tid < 128) {
        int n = n0 + tid;
        float b;
        if (MODE == 0) {
            if (n < NQ_)            b = bq[perm16(n >> 7, n & 127)];
            else if (n < NQ_+NKV_)  { int t = n - NQ_;        b = bk[perm4(t >> 7, t & 127)]; }
            else                    { int t = n - NQ_ - NKV_; b = bv[perm4(t >> 7, t & 127)]; }
        } else b = bq[n];
        sBias[tid] = b;
    }

    const __half* srcs[2] = { As + (size_t)m0 * D_, Bs + (size_t)n0 * D_ };

    auto load_stage = [&](int chunk) {
        const uint32_t st = sb + (uint32_t)(chunk % 3) * STAGE_GB;
        const int k0 = chunk * KC;
        #pragma unroll
        for (int t = 0; t < 2; t++) {
            const __half* s = srcs[t];
            const uint32_t tb = st + t * TILE_GB;
            #pragma unroll
            for (int it = 0; it < 4; it++) {
                int idx = tid + it * 256;
                int r = idx >> 3, c = idx & 7;
                cp_async16(tb + swz128(r, c), s + (size_t)r * D_ + k0 + c * 8);
            }
        }
        asm volatile("cp.async.commit_group;" ::: "memory");
    };

    float acc[2][8][4];
    #pragma unroll
    for (int mi = 0; mi < 2; mi++)
        #pragma unroll
        for (int ni = 0; ni < 8; ni++)
            #pragma unroll
            for (int q = 0; q < 4; q++) acc[mi][ni][q] = 0.f;

    const int mat = lane >> 3, rin = lane & 7;
    const int arow = wm*32 + (mat & 1)*8 + rin;
    const int acb  = (mat >> 1);
    const int brow = wn*64 + (mat >> 1)*8 + rin;
    const int bcb  = (mat & 1);

    load_stage(0);
    load_stage(1);

    for (int i = 0; i < NK; i++) {
        if (i >= NK - 1) asm volatile("cp.async.wait_group 0;" ::: "memory");
        else             asm volatile("cp.async.wait_group 1;" ::: "memory");
        __syncthreads();
        if (i + 2 < NK) load_stage(i + 2);

        const uint32_t st = sb + (uint32_t)(i % 3) * STAGE_GB;
        const uint32_t aA = st, bB = st + TILE_GB;

        #pragma unroll
        for (int kk = 0; kk < 4; kk++) {
            uint32_t af[2][4];
            #pragma unroll
            for (int mi = 0; mi < 2; mi++) {
                int r = arow + mi*16;
                ldsm4(af[mi], aA + swz128(r, kk*2 + acb));
            }
            uint32_t bf[8][2];
            #pragma unroll
            for (int nb2 = 0; nb2 < 4; nb2++) {
                int r = brow + nb2*16;
                uint32_t r4[4];
                ldsm4(r4, bB + swz128(r, kk*2 + bcb));
                bf[2*nb2][0] = r4[0]; bf[2*nb2][1] = r4[1];
                bf[2*nb2+1][0] = r4[2]; bf[2*nb2+1][1] = r4[3];
            }
            #pragma unroll
            for (int mi = 0; mi < 2; mi++)
                #pragma unroll
                for (int ni = 0; ni < 8; ni++)
                    mma16816(acc[mi][ni], af[mi], bf[ni]);
        }
    }

    // ---------- epilogue ----------
    const int g = lane >> 2, tig = lane & 3;
    #pragma unroll
    for (int mi = 0; mi < 2; mi++)
        #pragma unroll
        for (int ni = 0; ni < 8; ni++) {
            int col = wn*64 + ni*8 + tig*2;
            float b0 = sBias[col], b1 = sBias[col + 1];
            #pragma unroll
            for (int half = 0; half < 2; half++) {
                int row = m0 + wm*32 + mi*16 + g + half*8;
                float vx = acc[mi][ni][half*2+0] + b0;
                float vy = acc[mi][ni][half*2+1] + b1;
                if (MODE == 0) {
                    int bb = row >> 10, s = row & 1023;
                    __half2 hv = __half2(__float2half(vx), __float2half(vy));
                    if (n0 < NQ_) {
                        int h = n0 >> 7;
                        size_t o = ((size_t)((bb*H_ + h)*S_ + s))*DH_ + col;
                        *reinterpret_cast<__half2*>(g_Q + o) = hv;
                    } else if (n0 < NQ_+NKV_) {
                        int gg = (n0 - NQ_) >> 7;
                        size_t o = ((size_t)((bb*G_ + gg)*S_ + s))*DH_ + col;
                        *reinterpret_cast<__half2*>(g_K + o) = hv;
                    } else {
                        int gg = (n0 - NQ_ - NKV_) >> 7;
                        size_t o = ((size_t)(bb*G_ + gg)*DH_ + col)*S_ + s;
                        g_Vt[o]      = __float2half(vx);
                        g_Vt[o + S_] = __float2half(vy);
                    }
                } else {
                    *reinterpret_cast<float2*>(outp + (size_t)row * D_ + n0 + col) =
                        make_float2(vx, vy);
                }
            }
        }
}

// ================= fp16 flash attention, split-KV x2, fused 3-level PV =================
__global__ __launch_bounds__(512, 1)
void attn_mma_kernel()
{
    extern __shared__ char smem[];
    const uint32_t sb = smem_u32(smem);
    const int tid = threadIdx.x, lane = tid & 31, wid = tid >> 5;
    const int qt2 = (S_/QT - 1) - blockIdx.x;
    const int h = blockIdx.y;
    const int zz = blockIdx.z & 1, b = blockIdx.z >> 1;
    const int g = h >> 2;
    const int q0 = qt2 * QT;
    const int ktS = zz * (qt2 + 1);
    const int ktE = ktS + qt2 + 1;
    const int wq = (wid >> 1) * 16;
    const int wk = wid & 1;
    const int barid = 1 + (wid >> 1);
    const int mat = lane >> 3, rin = lane & 7;
    const int gq = lane >> 2, tig = lane & 3;

    const __half* Kp = g_K  + ((size_t)(b*G_ + g) * S_) * DH_;
    const __half* Vp = g_Vt + (size_t)(b*G_ + g) * DH_ * S_;
    const __half* Qp = g_Q  + ((size_t)(b*H_ + h) * S_ + q0) * DH_;

    auto issue_KV = [&](int kt) {
        const uint32_t kst = sb + K_OFF + (uint32_t)(kt & 1) * KTILE;
        const uint32_t vst = sb + V_OFF + (uint32_t)(kt & 1) * VTILE;
        const int k0 = kt * KT;
        #pragma unroll
        for (int i = 0; i < 2; i++) {
            int idx = tid + i * 512;
            { int r = idx >> 4, c = idx & 15;
              cp_async16(kst + swz256(r, c), Kp + (size_t)(k0 + r)*DH_ + c*8); }
            { int r = idx >> 3, c = idx & 7;
              cp_async16(vst + swz128(r, c), Vp + (size_t)r*S_ + k0 + c*8); }
        }
        asm volatile("cp.async.commit_group;" ::: "memory");
    };

    #pragma unroll
    for (int i = 0; i < 4; i++) {
        int idx = tid + i * 512; int r = idx >> 4, c = idx & 15;
        cp_async16(sb + swz256(r, c), Qp + (size_t)r*DH_ + c*8);
    }
    issue_KV(ktS);

    float o0[2][4] = {}, o1[2][4] = {}, o2[4][4] = {};
    float lsum[3][2] = {};

    const int rq = wq + (mat & 1)*8 + rin;
    const uint32_t qrow_off = (uint32_t)rq * 256;
    const int qsw = rq & 7;
    const uint32_t prow_off = (uint32_t)rq * 128;
    char* pwp = smem + P_OFF;
    float* lred = reinterpret_cast<float*>(smem + P_OFF);

    for (int kt = ktS; kt < ktE; kt++) {
        asm volatile("cp.async.wait_group 0;" ::: "memory");
        __syncthreads();
        if (kt + 1 < ktE) issue_KV(kt + 1);

        const int k0 = kt * KT;
        const uint32_t kst = sb + K_OFF + (uint32_t)(kt & 1) * KTILE;
        const uint32_t vst = sb + V_OFF + (uint32_t)(kt & 1) * VTILE;

        float acc[4][4];
        #pragma unroll
        for (int nb = 0; nb < 4; nb++)
            #pragma unroll
            for (int q = 0; q < 4; q++) acc[nb][q] = 0.f;

        auto qk_steps = [&](int kkA, int kkB) {
            #pragma unroll
            for (int kk = kkA; kk < kkB; kk++) {
                uint32_t qh[4];
                uint32_t qoff = qrow_off + (uint32_t)(((kk*2 + (mat>>1)) ^ qsw) << 4);
                ldsm4(qh, sb + qoff);
                uint32_t bh[4][2];
                #pragma unroll
                for (int nb2 = 0; nb2 < 2; nb2++) {
                    int rk = wk*32 + nb2*16 + (mat >> 1)*8 + rin;
                    uint32_t off = swz256(rk, kk*2 + (mat & 1));
                    uint32_t r4[4];
                    ldsm4(r4, kst + off);
                    bh[2*nb2][0] = r4[0]; bh[2*nb2][1] = r4[1];
                    bh[2*nb2+1][0] = r4[2]; bh[2*nb2+1][1] = r4[3];
                }
                #pragma unroll
                for (int nb = 0; nb < 4; nb++) mma16816(acc[nb], qh, bh[nb]);
            }
        };

        auto do_exp = [&](float scale, float* ls, int L) {
            const int r0g = q0 + wq + gq, r1g = r0g + 8;
            const bool need_mask = (k0 + wk*32 + 31 > q0 + wq);
            char* pL = pwp + L * PTILE;
            #pragma unroll
            for (int nb = 0; nb < 4; nb++) {
                int colg = k0 + wk*32 + nb*8 + tig*2;
                float p0 = __expf(acc[nb][0] * scale);
                float p1 = __expf(acc[nb][1] * scale);
                float p2 = __expf(acc[nb][2] * scale);
                float p3 = __expf(acc[nb][3] * scale);
                if (need_mask) {
                    if (colg     > r0g) p0 = 0.f;
                    if (colg + 1 > r0g) p1 = 0.f;
                    if (colg     > r1g) p2 = 0.f;
                    if (colg + 1 > r1g) p3 = 0.f;
                }
                ls[0] += p0 + p1; ls[1] += p2 + p3;
                int rw0 = wq + gq, rw1 = rw0 + 8;
                int c = wk*4 + nb;
                uint32_t o0b = swz128(rw0, c) + tig*4;
                uint32_t o1b = swz128(rw1, c) + tig*4;
                *reinterpret_cast<__half2*>(pL + o0b) =
                    __half2(__float2half(p0), __float2half(p1));
                *reinterpret_cast<__half2*>(pL + o1b) =
                    __half2(__float2half(p2), __float2half(p3));
            }
        };

        qk_steps(0, 2);
        do_exp(SCALE0, lsum[0], 0);
        qk_steps(2, 4);
        do_exp(SCALE1, lsum[1], 1);
        qk_steps(4, 8);
        do_exp(SCALE2, lsum[2], 2);
        bar_pair(barid);

        // fused PV across all 3 levels
        #pragma unroll
        for (int kk2 = 0; kk2 < 4; kk2++) {
            uint32_t poff = prow_off + (uint32_t)(((kk2*2 + (mat>>1)) ^ qsw) << 4);
            uint32_t p0f[4], p1f[4], p2f[4];
            ldsm4(p0f, sb + P_OFF + poff);
            ldsm4(p1f, sb + P_OFF + PTILE + poff);
            ldsm4(p2f, sb + P_OFF + 2*PTILE + poff);
            // V rows for level0/1 (1 frag each) and level2 (2 frags)
            {
                int rv = wk*16 + (mat >> 1)*8 + rin;
                uint32_t r4[4];
                ldsm4(r4, vst + swz128(rv, kk2*2 + (mat & 1)));
                uint32_t v0[2] = {r4[0], r4[1]}, v1[2] = {r4[2], r4[3]};
                mma16816(o0[0], p0f, v0);
                mma16816(o0[1], p0f, v1);
            }
            {
                int rv = 32 + wk*16 + (mat >> 1)*8 + rin;
                uint32_t r4[4];
                ldsm4(r4, vst + swz128(rv, kk2*2 + (mat & 1)));
                uint32_t v0[2] = {r4[0], r4[1]}, v1[2] = {r4[2], r4[3]};
                mma16816(o1[0], p1f, v0);
                mma16816(o1[1], p1f, v1);
            }
            #pragma unroll
            for (int nb2 = 0; nb2 < 2; nb2++) {
                int rv = 64 + wk*32 + nb2*16 + (mat >> 1)*8 + rin;
                uint32_t r4[4];
                ldsm4(r4, vst + swz128(rv, kk2*2 + (mat & 1)));
                uint32_t v0[2] = {r4[0], r4[1]}, v1[2] = {r4[2], r4[3]};
                mma16816(o2[2*nb2],   p2f, v0);
                mma16816(o2[2*nb2+1], p2f, v1);
            }
        }
        bar_pair(barid);
    }

    #pragma unroll
    for (int L = 0; L < 3; L++)
        #pragma unroll
        for (int j = 0; j < 2; j++) {
            lsum[L][j] += __shfl_xor_sync(0xffffffffu, lsum[L][j], 1);
            lsum[L][j] += __shfl_xor_sync(0xffffffffu, lsum[L][j], 2);
        }
    __syncthreads();
    if (tig == 0) {
        #pragma unroll
        for (int L = 0; L < 3; L++) {
            lred[L*256 + (wq + gq)*2 + wk]     = lsum[L][0];
            lred[L*256 + (wq + gq + 8)*2 + wk] = lsum[L][1];
        }
    }
    __syncthreads();

    const int r0 = wq + gq, r1 = r0 + 8;

    if (wk == 0 && tig == 0) {
        int idx0 = (b*H_ + h)*S_ + q0 + r0;
        int idx1 = idx0 + 8;
        #pragma unroll
        for (int L = 0; L < 3; L++) {
            g_lsum[(zz*3 + L)*BHS_ + idx0] = lred[L*256 + r0*2] + lred[L*256 + r0*2 + 1];
            g_lsum[(zz*3 + L)*BHS_ + idx1] = lred[L*256 + r1*2] + lred[L*256 + r1*2 + 1];
        }
    }

    float* part = g_part + (size_t)zz * PZ_;
    size_t base0 = ((size_t)(b*S_ + q0 + r0)) * D_ + (size_t)h * DH_;
    size_t base1 = ((size_t)(b*S_ + q0 + r1)) * D_ + (size_t)h * DH_;
    #pragma unroll
    for (int j = 0; j < 2; j++) {
        int d = wk*16 + j*8 + tig*2;
        *reinterpret_cast<float2*>(part + base0 + d)      = make_float2(o0[j][0], o0[j][1]);
        *reinterpret_cast<float2*>(part + base1 + d)      = make_float2(o0[j][2], o0[j][3]);
        *reinterpret_cast<float2*>(part + base0 + 32 + d) = make_float2(o1[j][0], o1[j][1]);
        *reinterpret_cast<float2*>(part + base1 + 32 + d) = make_float2(o1[j][2], o1[j][3]);
    }
    #pragma unroll
    for (int j = 0; j < 4; j++) {
        int d = 64 + wk*32 + j*8 + tig*2;
        *reinterpret_cast<float2*>(part + base0 + d) = make_float2(o2[j][0], o2[j][1]);
        *reinterpret_cast<float2*>(part + base1 + d) = make_float2(o2[j][2], o2[j][3]);
    }
}

// ================= attention combine =================
__global__ __launch_bounds__(256)
void attn_combine()
{
    const int m = blockIdx.x;
    const int col = blockIdx.y * 512 + threadIdx.x * 2;
    float2 p0 = *reinterpret_cast<const float2*>(g_part + (size_t)m*D_ + col);
    float2 p1 = *reinterpret_cast<const float2*>(g_part + PZ_ + (size_t)m*D_ + col);
    const int h = col >> 7, d = col & 127;
    const int L = (d < 32) ? 0 : (d < 64) ? 1 : 2;
    const int b = m >> 10, s = m & 1023;
    const int idx = (b*H_ + h)*S_ + s;
    float ls = g_lsum[L*BHS_ + idx] + g_lsum[(3 + L)*BHS_ + idx];
    float inv = 1.f / ls;
    size_t o = (size_t)m * D_ + col;
    *reinterpret_cast<__half2*>(g_AO + o) =
        __half2(__float2half((p0.x + p1.x) * inv), __float2half((p0.y + p1.y) * inv));
}

// ================= launch =================
extern "C" void kernel_launch(void* const* d_in, const int* in_sizes, int n_in,
                              void* d_out, int out_size)
{
    (void)in_sizes; (void)n_in; (void)out_size;
    const float* x  = (const float*)d_in[0];
    const float* Wq = (const float*)d_in[2];
    const float* bq = (const float*)d_in[3];
    const float* Wk = (const float*)d_in[4];
    const float* bk = (const float*)d_in[5];
    const float* Wv = (const float*)d_in[6];
    const float* bv = (const float*)d_in[7];
    const float* Wo = (const float*)d_in[8];
    const float* bo = (const float*)d_in[9];
    float* out = (float*)d_out;

    convx_kernel<<<MROWS_*D_/4/256, 256>>>(x);
    tconv_qkv_kernel<<<dim3(NTOT_/64, D_/64), 256>>>(Wq, Wk, Wv);
    tconv_wo_kernel<<<dim3(D_/64, D_/64), 256>>>(Wo);

    static __half *px = nullptr, *pwt, *pwot, *pao;
    if (!px) {
        cudaGetSymbolAddress((void**)&px, g_x);
        cudaGetSymbolAddress((void**)&pwt, g_Wt);
        cudaGetSymbolAddress((void**)&pwot, g_Wot);
        cudaGetSymbolAddress((void**)&pao, g_AO);
    }

    static bool attr_set = false;
    if (!attr_set) {
        cudaFuncSetAttribute(gemm_mma_kernel<0>, cudaFuncAttributeMaxDynamicSharedMemorySize, GEMM_SMEM);
        cudaFuncSetAttribute(gemm_mma_kernel<1>, cudaFuncAttributeMaxDynamicSharedMemorySize, GEMM_SMEM);
        cudaFuncSetAttribute(attn_mma_kernel, cudaFuncAttributeMaxDynamicSharedMemorySize, ATT_SMEM);
        attr_set = true;
    }

    gemm_mma_kernel<0><<<dim3(NTOT_/128, MROWS_/128), 256, GEMM_SMEM>>>(
        px, pwt, nullptr, bq, bk, bv);

    attn_mma_kernel<<<dim3(S_/QT, H_, B_*2), 512, ATT_SMEM>>>();
    attn_combine<<<dim3(MROWS_, 4), 256>>>();

    gemm_mma_kernel<1><<<dim3(D_/128, MROWS_/128), 256, GEMM_SMEM>>>(
        pao, pwot, out, bo, nullptr, nullptr);
}